// round 1
// baseline (speedup 1.0000x reference)
#include <cuda_runtime.h>
#include <math.h>

#define H_  80
#define W_  80
#define HW  6400
#define C_  256
#define CP  19
#define KS  7
#define K2  49

// Scratch (allocation-free: __device__ globals)
__device__ float g_wp[C_ * C_];     // BN-folded w_feat
__device__ float g_bias[C_];        // BN-folded bias
__device__ float g_msg[C_ * HW];    // messages
__device__ float g_agg[C_ * HW];    // aggregated
__device__ float g_aff[K2 * HW];    // unnormalized affinity exp(exp(-d/denom))
__device__ float g_inv[HW];         // 1 / sum_k2 of the above

// ---------------------------------------------------------------------------
// Fold BN into the feature conv: w'[o][c] = w[o][c]*a_c, bias[o] = sum w*b_c
// ---------------------------------------------------------------------------
__global__ void prep_kernel(const float* __restrict__ wfeat,
                            const float* __restrict__ gamma,
                            const float* __restrict__ beta,
                            const float* __restrict__ mean,
                            const float* __restrict__ var) {
    int o = blockIdx.x;
    int c = threadIdx.x;
    float a = gamma[c] * rsqrtf(var[c] + 1e-5f);
    float b = beta[c] - mean[c] * a;
    float w = wfeat[o * C_ + c];
    g_wp[o * C_ + c] = w * a;

    __shared__ float red[C_];
    red[c] = w * b;
    __syncthreads();
    for (int s = C_ / 2; s > 0; s >>= 1) {
        if (c < s) red[c] += red[c + s];
        __syncthreads();
    }
    if (c == 0) g_bias[o] = red[0];
}

// ---------------------------------------------------------------------------
// Affinity: per pixel, 49 distances over 19 channels; store exp(exp(-d/denom))
// and the reciprocal of their sum (softmax normalization deferred).
// ---------------------------------------------------------------------------
__global__ void __launch_bounds__(128) affinity_kernel(
        const float* __restrict__ coarse,
        const float* __restrict__ sigma) {
    int p = blockIdx.x * blockDim.x + threadIdx.x;
    if (p >= HW) return;
    int h = p / W_, w = p - h * W_;

    float sr = fmaxf(sigma[0], 0.0f);
    float invd = 1.0f / (2.0f * sr * sr + 1e-8f);

    float center[CP];
    float c2 = 0.0f;
#pragma unroll
    for (int cp = 0; cp < CP; cp++) {
        float v = coarse[cp * HW + p];
        center[cp] = v;
        c2 += v * v;   // distance when neighbor is zero-padded
    }

    float sum = 0.0f;
    for (int i = 0; i < KS; i++) {
        int hh = h + i - 3;
        for (int j = 0; j < KS; j++) {
            int ww = w + j - 3;
            float d;
            if (hh >= 0 && hh < H_ && ww >= 0 && ww < W_) {
                int q = hh * W_ + ww;
                d = 0.0f;
#pragma unroll
                for (int cp = 0; cp < CP; cp++) {
                    float t = coarse[cp * HW + q] - center[cp];
                    d += t * t;
                }
            } else {
                d = c2;
            }
            float e = expf(expf(-d * invd));
            g_aff[(i * KS + j) * HW + p] = e;
            sum += e;
        }
    }
    g_inv[p] = 1.0f / sum;
}

// ---------------------------------------------------------------------------
// SGEMM: C[M=256, N=6400] = A[256,256] * B[256,6400] (+ bias[row] | + resid)
// 64x128 block tile, BK=16, 256 threads, 4x8 microtile.
// ---------------------------------------------------------------------------
#define BM 64
#define BN 128
#define BK 16

__global__ void __launch_bounds__(256) gemm_kernel(
        const float* __restrict__ A,
        const float* __restrict__ B,
        float* __restrict__ Cout,
        const float* __restrict__ bias,    // may be null
        const float* __restrict__ resid) { // may be null
    const int N = HW;
    const int Kd = C_;

    __shared__ float As[BK][BM];
    __shared__ float Bs[BK][BN];

    int n0 = blockIdx.x * BN;
    int m0 = blockIdx.y * BM;
    int t  = threadIdx.x;
    int tx = t & 15;     // 0..15 -> N
    int ty = t >> 4;     // 0..15 -> M

    // A-load: 1024 floats = 256 float4; B-load: 2048 floats = 2 float4/thread
    int ar = t >> 2;          // 0..63
    int ac = (t & 3) * 4;     // 0,4,8,12
    int br = t >> 5;          // 0..7
    int bc = (t & 31) * 4;    // 0..124

    float acc[4][8];
#pragma unroll
    for (int i = 0; i < 4; i++)
#pragma unroll
        for (int j = 0; j < 8; j++) acc[i][j] = 0.0f;

    for (int k0 = 0; k0 < Kd; k0 += BK) {
        float4 av = *(const float4*)(A + (m0 + ar) * Kd + k0 + ac);
        As[ac + 0][ar] = av.x;
        As[ac + 1][ar] = av.y;
        As[ac + 2][ar] = av.z;
        As[ac + 3][ar] = av.w;
        float4 bv0 = *(const float4*)(B + (k0 + br) * N + n0 + bc);
        float4 bv1 = *(const float4*)(B + (k0 + br + 8) * N + n0 + bc);
        *(float4*)&Bs[br][bc]     = bv0;
        *(float4*)&Bs[br + 8][bc] = bv1;
        __syncthreads();

#pragma unroll
        for (int kk = 0; kk < BK; kk++) {
            float a[4], b[8];
            *(float4*)a       = *(const float4*)&As[kk][ty * 4];
            *(float4*)b       = *(const float4*)&Bs[kk][tx * 8];
            *(float4*)(b + 4) = *(const float4*)&Bs[kk][tx * 8 + 4];
#pragma unroll
            for (int i = 0; i < 4; i++)
#pragma unroll
                for (int j = 0; j < 8; j++)
                    acc[i][j] += a[i] * b[j];
        }
        __syncthreads();
    }

#pragma unroll
    for (int i = 0; i < 4; i++) {
        int row = m0 + ty * 4 + i;
        float badd = bias ? bias[row] : 0.0f;
#pragma unroll
        for (int j4 = 0; j4 < 8; j4 += 4) {
            int col = n0 + tx * 8 + j4;
            float4 r;
            r.x = acc[i][j4 + 0] + badd;
            r.y = acc[i][j4 + 1] + badd;
            r.z = acc[i][j4 + 2] + badd;
            r.w = acc[i][j4 + 3] + badd;
            if (resid) {
                float4 rv = *(const float4*)(resid + row * N + col);
                r.x += rv.x; r.y += rv.y; r.z += rv.z; r.w += rv.w;
            }
            *(float4*)(Cout + row * N + col) = r;
        }
    }
}

// ---------------------------------------------------------------------------
// Aggregation: agg[c,p] = (sum_k2 msg[c, p+off(k2)] * affE[k2,p]) * inv[p]
// One block per (row h, group of 32 channels). Affinity row in SMEM
// (normalization folded in at load). 8 channels per thread.
// ---------------------------------------------------------------------------
#define CPT 8

__global__ void __launch_bounds__(320) agg_kernel() {
    int h  = blockIdx.x;          // 0..79
    int w  = threadIdx.x;         // 0..79
    int cy = threadIdx.y;         // 0..3
    int cbase = (blockIdx.y * 4 + cy) * CPT;

    __shared__ float saff[K2][W_];
    int tid = cy * W_ + w;
    const float* affrow = g_aff + h * W_;
    const float* invrow = g_inv + h * W_;
    for (int idx = tid; idx < K2 * W_; idx += 4 * W_) {
        int k2 = idx / W_;
        int ww = idx - k2 * W_;
        saff[k2][ww] = affrow[k2 * HW + ww] * invrow[ww];
    }
    __syncthreads();

    float acc[CPT];
#pragma unroll
    for (int cc = 0; cc < CPT; cc++) acc[cc] = 0.0f;

    const float* msgc = g_msg + cbase * HW;
    for (int i = 0; i < KS; i++) {
        int hh = h + i - 3;
        if (hh < 0 || hh >= H_) continue;
#pragma unroll
        for (int j = 0; j < KS; j++) {
            int ww = w + j - 3;
            if (ww < 0 || ww >= W_) continue;
            float a = saff[i * KS + j][w];
            const float* m = msgc + hh * W_ + ww;
#pragma unroll
            for (int cc = 0; cc < CPT; cc++)
                acc[cc] += m[cc * HW] * a;
        }
    }
#pragma unroll
    for (int cc = 0; cc < CPT; cc++)
        g_agg[(cbase + cc) * HW + h * W_ + w] = acc[cc];
}

// ---------------------------------------------------------------------------
// Launch
// ---------------------------------------------------------------------------
extern "C" void kernel_launch(void* const* d_in, const int* in_sizes, int n_in,
                              void* d_out, int out_size) {
    const float* x      = (const float*)d_in[0];
    const float* coarse = (const float*)d_in[1];
    const float* sigma  = (const float*)d_in[2];
    const float* wfeat  = (const float*)d_in[3];
    const float* wfuse  = (const float*)d_in[4];
    const float* gamma  = (const float*)d_in[5];
    const float* beta   = (const float*)d_in[6];
    const float* mean   = (const float*)d_in[7];
    const float* var    = (const float*)d_in[8];
    float* out = (float*)d_out;

    float *wp, *bias, *msg, *agg;
    cudaGetSymbolAddress((void**)&wp,   g_wp);
    cudaGetSymbolAddress((void**)&bias, g_bias);
    cudaGetSymbolAddress((void**)&msg,  g_msg);
    cudaGetSymbolAddress((void**)&agg,  g_agg);

    prep_kernel<<<C_, C_>>>(wfeat, gamma, beta, mean, var);
    affinity_kernel<<<(HW + 127) / 128, 128>>>(coarse, sigma);
    // messages = w' @ x + bias
    gemm_kernel<<<dim3(HW / BN, C_ / BM), 256>>>(wp, x, msg, bias, nullptr);
    // spatially-varying 7x7 aggregation with softmax affinity
    agg_kernel<<<dim3(H_, C_ / (4 * CPT)), dim3(W_, 4)>>>();
    // out = x + w_fuse @ agg
    gemm_kernel<<<dim3(HW / BN, C_ / BM), 256>>>(wfuse, agg, out, nullptr, x);
}

// round 2
// speedup vs baseline: 1.0433x; 1.0433x over previous
#include <cuda_runtime.h>
#include <math.h>

#define H_  80
#define W_  80
#define HW  6400
#define C_  256
#define CP  19
#define KS  7
#define K2  49

// Scratch (allocation-free: __device__ globals)
__device__ float g_wp[C_ * C_];     // BN-folded w_feat
__device__ float g_bias[C_];        // BN-folded bias
__device__ float g_msg[C_ * HW];    // messages
__device__ float g_agg[C_ * HW];    // aggregated
__device__ float g_aff[K2 * HW];    // unnormalized affinity exp(exp(-d/denom))
__device__ float g_inv[HW];         // 1 / sum_k2 of the above

// ---------------------------------------------------------------------------
// Fold BN into the feature conv: w'[o][c] = w[o][c]*a_c, bias[o] = sum w*b_c
// ---------------------------------------------------------------------------
__global__ void prep_kernel(const float* __restrict__ wfeat,
                            const float* __restrict__ gamma,
                            const float* __restrict__ beta,
                            const float* __restrict__ mean,
                            const float* __restrict__ var) {
    int o = blockIdx.x;
    int c = threadIdx.x;
    float a = gamma[c] * rsqrtf(var[c] + 1e-5f);
    float b = beta[c] - mean[c] * a;
    float w = wfeat[o * C_ + c];
    g_wp[o * C_ + c] = w * a;

    __shared__ float red[C_];
    red[c] = w * b;
    __syncthreads();
    for (int s = C_ / 2; s > 0; s >>= 1) {
        if (c < s) red[c] += red[c + s];
        __syncthreads();
    }
    if (c == 0) g_bias[o] = red[0];
}

// ---------------------------------------------------------------------------
// Affinity: per pixel, 49 distances over 19 channels; store exp(exp(-d/denom))
// and the reciprocal of their sum (softmax normalization deferred).
// ---------------------------------------------------------------------------
__global__ void __launch_bounds__(128) affinity_kernel(
        const float* __restrict__ coarse,
        const float* __restrict__ sigma) {
    int p = blockIdx.x * blockDim.x + threadIdx.x;
    if (p >= HW) return;
    int h = p / W_, w = p - h * W_;

    float sr = fmaxf(sigma[0], 0.0f);
    float invd = 1.0f / (2.0f * sr * sr + 1e-8f);

    float center[CP];
    float c2 = 0.0f;
#pragma unroll
    for (int cp = 0; cp < CP; cp++) {
        float v = coarse[cp * HW + p];
        center[cp] = v;
        c2 += v * v;   // distance when neighbor is zero-padded
    }

    float sum = 0.0f;
    for (int i = 0; i < KS; i++) {
        int hh = h + i - 3;
        for (int j = 0; j < KS; j++) {
            int ww = w + j - 3;
            float d;
            if (hh >= 0 && hh < H_ && ww >= 0 && ww < W_) {
                int q = hh * W_ + ww;
                d = 0.0f;
#pragma unroll
                for (int cp = 0; cp < CP; cp++) {
                    float t = coarse[cp * HW + q] - center[cp];
                    d += t * t;
                }
            } else {
                d = c2;
            }
            float e = expf(expf(-d * invd));
            g_aff[(i * KS + j) * HW + p] = e;
            sum += e;
        }
    }
    g_inv[p] = 1.0f / sum;
}

// ---------------------------------------------------------------------------
// SGEMM: C[M=256, N=6400] = A[256,256] * B[256,6400] (+ bias[row] | + resid)
// 64x128 block tile, BK=16, 256 threads, 4x8 microtile.
// ---------------------------------------------------------------------------
#define BM 64
#define BN 128
#define BK 16

__global__ void __launch_bounds__(256) gemm_kernel(
        const float* __restrict__ A,
        const float* __restrict__ B,
        float* __restrict__ Cout,
        const float* __restrict__ bias,    // may be null
        const float* __restrict__ resid) { // may be null
    const int N = HW;
    const int Kd = C_;

    __shared__ float As[BK][BM];
    __shared__ float Bs[BK][BN];

    int n0 = blockIdx.x * BN;
    int m0 = blockIdx.y * BM;
    int t  = threadIdx.x;
    int tx = t & 15;     // 0..15 -> N
    int ty = t >> 4;     // 0..15 -> M

    // A-load: 1024 floats = 256 float4; B-load: 2048 floats = 2 float4/thread
    int ar = t >> 2;          // 0..63
    int ac = (t & 3) * 4;     // 0,4,8,12
    int br = t >> 5;          // 0..7
    int bc = (t & 31) * 4;    // 0..124

    float acc[4][8];
#pragma unroll
    for (int i = 0; i < 4; i++)
#pragma unroll
        for (int j = 0; j < 8; j++) acc[i][j] = 0.0f;

    for (int k0 = 0; k0 < Kd; k0 += BK) {
        float4 av = *(const float4*)(A + (m0 + ar) * Kd + k0 + ac);
        As[ac + 0][ar] = av.x;
        As[ac + 1][ar] = av.y;
        As[ac + 2][ar] = av.z;
        As[ac + 3][ar] = av.w;
        float4 bv0 = *(const float4*)(B + (k0 + br) * N + n0 + bc);
        float4 bv1 = *(const float4*)(B + (k0 + br + 8) * N + n0 + bc);
        *(float4*)&Bs[br][bc]     = bv0;
        *(float4*)&Bs[br + 8][bc] = bv1;
        __syncthreads();

#pragma unroll
        for (int kk = 0; kk < BK; kk++) {
            float a[4], b[8];
            *(float4*)a       = *(const float4*)&As[kk][ty * 4];
            *(float4*)b       = *(const float4*)&Bs[kk][tx * 8];
            *(float4*)(b + 4) = *(const float4*)&Bs[kk][tx * 8 + 4];
#pragma unroll
            for (int i = 0; i < 4; i++)
#pragma unroll
                for (int j = 0; j < 8; j++)
                    acc[i][j] += a[i] * b[j];
        }
        __syncthreads();
    }

#pragma unroll
    for (int i = 0; i < 4; i++) {
        int row = m0 + ty * 4 + i;
        float badd = bias ? bias[row] : 0.0f;
#pragma unroll
        for (int j4 = 0; j4 < 8; j4 += 4) {
            int col = n0 + tx * 8 + j4;
            float4 r;
            r.x = acc[i][j4 + 0] + badd;
            r.y = acc[i][j4 + 1] + badd;
            r.z = acc[i][j4 + 2] + badd;
            r.w = acc[i][j4 + 3] + badd;
            if (resid) {
                float4 rv = *(const float4*)(resid + row * N + col);
                r.x += rv.x; r.y += rv.y; r.z += rv.z; r.w += rv.w;
            }
            *(float4*)(Cout + row * N + col) = r;
        }
    }
}

// ---------------------------------------------------------------------------
// Aggregation: agg[c,p] = (sum_k2 msg[c, p+off(k2)] * affE[k2,p]) * inv[p]
// One block per (row h, group of 32 channels). Affinity row in SMEM
// (normalization folded in at load). 8 channels per thread.
// ---------------------------------------------------------------------------
#define CPT 8

__global__ void __launch_bounds__(320) agg_kernel() {
    int h  = blockIdx.x;          // 0..79
    int w  = threadIdx.x;         // 0..79
    int cy = threadIdx.y;         // 0..3
    int cbase = (blockIdx.y * 4 + cy) * CPT;

    __shared__ float saff[K2][W_];
    int tid = cy * W_ + w;
    const float* affrow = g_aff + h * W_;
    const float* invrow = g_inv + h * W_;
    for (int idx = tid; idx < K2 * W_; idx += 4 * W_) {
        int k2 = idx / W_;
        int ww = idx - k2 * W_;
        saff[k2][ww] = affrow[k2 * HW + ww] * invrow[ww];
    }
    __syncthreads();

    float acc[CPT];
#pragma unroll
    for (int cc = 0; cc < CPT; cc++) acc[cc] = 0.0f;

    const float* msgc = g_msg + cbase * HW;
    for (int i = 0; i < KS; i++) {
        int hh = h + i - 3;
        if (hh < 0 || hh >= H_) continue;
#pragma unroll
        for (int j = 0; j < KS; j++) {
            int ww = w + j - 3;
            if (ww < 0 || ww >= W_) continue;
            float a = saff[i * KS + j][w];
            const float* m = msgc + hh * W_ + ww;
#pragma unroll
            for (int cc = 0; cc < CPT; cc++)
                acc[cc] += m[cc * HW] * a;
        }
    }
#pragma unroll
    for (int cc = 0; cc < CPT; cc++)
        g_agg[(cbase + cc) * HW + h * W_ + w] = acc[cc];
}

// ---------------------------------------------------------------------------
// Launch
// ---------------------------------------------------------------------------
extern "C" void kernel_launch(void* const* d_in, const int* in_sizes, int n_in,
                              void* d_out, int out_size) {
    const float* x      = (const float*)d_in[0];
    const float* coarse = (const float*)d_in[1];
    const float* sigma  = (const float*)d_in[2];
    const float* wfeat  = (const float*)d_in[3];
    const float* wfuse  = (const float*)d_in[4];
    const float* gamma  = (const float*)d_in[5];
    const float* beta   = (const float*)d_in[6];
    const float* mean   = (const float*)d_in[7];
    const float* var    = (const float*)d_in[8];
    float* out = (float*)d_out;

    float *wp, *bias, *msg, *agg;
    cudaGetSymbolAddress((void**)&wp,   g_wp);
    cudaGetSymbolAddress((void**)&bias, g_bias);
    cudaGetSymbolAddress((void**)&msg,  g_msg);
    cudaGetSymbolAddress((void**)&agg,  g_agg);

    prep_kernel<<<C_, C_>>>(wfeat, gamma, beta, mean, var);
    affinity_kernel<<<(HW + 127) / 128, 128>>>(coarse, sigma);
    // messages = w' @ x + bias
    gemm_kernel<<<dim3(HW / BN, C_ / BM), 256>>>(wp, x, msg, bias, nullptr);
    // spatially-varying 7x7 aggregation with softmax affinity
    agg_kernel<<<dim3(H_, C_ / (4 * CPT)), dim3(W_, 4)>>>();
    // out = x + w_fuse @ agg
    gemm_kernel<<<dim3(HW / BN, C_ / BM), 256>>>(wfuse, agg, out, nullptr, x);
}

// round 3
// speedup vs baseline: 1.8486x; 1.7718x over previous
#include <cuda_runtime.h>
#include <math.h>

#define H_  80
#define W_  80
#define HW  6400
#define C_  256
#define CP  19
#define KS  7
#define K2  49

// Scratch (allocation-free: __device__ globals)
__device__ float g_wp[C_ * C_];     // BN-folded w_feat
__device__ float g_bias[C_];        // BN-folded bias
__device__ float g_msg[C_ * HW];    // messages
__device__ float g_agg[C_ * HW];    // aggregated
__device__ float g_aff[K2 * HW];    // unnormalized affinity exp(exp(-d/denom))
__device__ float g_inv[HW];         // 1 / sum_k2 of the above

// ---------------------------------------------------------------------------
// Fold BN into the feature conv: w'[o][c] = w[o][c]*a_c, bias[o] = sum w*b_c
// ---------------------------------------------------------------------------
__global__ void prep_kernel(const float* __restrict__ wfeat,
                            const float* __restrict__ gamma,
                            const float* __restrict__ beta,
                            const float* __restrict__ mean,
                            const float* __restrict__ var) {
    int o = blockIdx.x;
    int c = threadIdx.x;
    float a = gamma[c] * rsqrtf(var[c] + 1e-5f);
    float b = beta[c] - mean[c] * a;
    float w = wfeat[o * C_ + c];
    g_wp[o * C_ + c] = w * a;

    __shared__ float red[C_];
    red[c] = w * b;
    __syncthreads();
    for (int s = C_ / 2; s > 0; s >>= 1) {
        if (c < s) red[c] += red[c + s];
        __syncthreads();
    }
    if (c == 0) g_bias[o] = red[0];
}

// ---------------------------------------------------------------------------
// Affinity: per pixel, 49 distances over 19 channels; store exp(exp(-d/denom))
// and the reciprocal of their sum (softmax normalization deferred).
// ---------------------------------------------------------------------------
__global__ void __launch_bounds__(128) affinity_kernel(
        const float* __restrict__ coarse,
        const float* __restrict__ sigma) {
    int p = blockIdx.x * blockDim.x + threadIdx.x;
    if (p >= HW) return;
    int h = p / W_, w = p - h * W_;

    float sr = fmaxf(sigma[0], 0.0f);
    float invd = 1.0f / (2.0f * sr * sr + 1e-8f);

    float center[CP];
    float c2 = 0.0f;
#pragma unroll
    for (int cp = 0; cp < CP; cp++) {
        float v = coarse[cp * HW + p];
        center[cp] = v;
        c2 += v * v;   // distance when neighbor is zero-padded
    }

    float sum = 0.0f;
    for (int i = 0; i < KS; i++) {
        int hh = h + i - 3;
        for (int j = 0; j < KS; j++) {
            int ww = w + j - 3;
            float d;
            if (hh >= 0 && hh < H_ && ww >= 0 && ww < W_) {
                int q = hh * W_ + ww;
                d = 0.0f;
#pragma unroll
                for (int cp = 0; cp < CP; cp++) {
                    float t = coarse[cp * HW + q] - center[cp];
                    d += t * t;
                }
            } else {
                d = c2;
            }
            float e = expf(expf(-d * invd));
            g_aff[(i * KS + j) * HW + p] = e;
            sum += e;
        }
    }
    g_inv[p] = 1.0f / sum;
}

// ---------------------------------------------------------------------------
// Tensor-core GEMM (tf32 mma.sync): C[256,6400] = A[256,256] * B[256,6400]
// 128x128 block tile, BK=32, 8 warps (2x4), warp tile 64x32 (4x4 m16n8k8).
// ---------------------------------------------------------------------------
#define TBM 128
#define TBN 128
#define TBK 32

__device__ __forceinline__ float f2tf32(float x) {
    unsigned r;
    asm("cvt.rna.tf32.f32 %0, %1;" : "=r"(r) : "f"(x));
    return __uint_as_float(r);
}

__device__ __forceinline__ void mma_tf32(float* c, const unsigned* a, const unsigned* b) {
    asm volatile(
        "mma.sync.aligned.m16n8k8.row.col.f32.tf32.tf32.f32 "
        "{%0,%1,%2,%3}, {%4,%5,%6,%7}, {%8,%9}, {%0,%1,%2,%3};\n"
        : "+f"(c[0]), "+f"(c[1]), "+f"(c[2]), "+f"(c[3])
        : "r"(a[0]), "r"(a[1]), "r"(a[2]), "r"(a[3]), "r"(b[0]), "r"(b[1]));
}

__global__ void __launch_bounds__(256) gemm_tc(
        const float* __restrict__ A,      // [C_ x C_] row-major
        const float* __restrict__ B,      // [C_ x HW]
        float* __restrict__ Cout,         // [C_ x HW]
        const float* __restrict__ bias,   // may be null
        const float* __restrict__ resid) {// may be null
    const int N = HW, Kd = C_;
    __shared__ float As[TBM][TBK + 4];    // pad -> frag bank = 4*gid+tig (conflict-free)
    __shared__ float Bs[TBK][TBN + 8];    // pad -> frag bank = 8*tig+gid (conflict-free)

    int t    = threadIdx.x;
    int warp = t >> 5, lane = t & 31;
    int gid  = lane >> 2, tig = lane & 3;
    int wm   = warp >> 2, wn = warp & 3;      // 2 x 4 warps
    int m0   = blockIdx.y * TBM, n0 = blockIdx.x * TBN;

    // tile-load indexing
    int ar  = t >> 1;             // 0..127 (A row)
    int ac  = (t & 1) * 16;       // 0 or 16
    int bkr = t >> 3;             // 0..31  (B k-row)
    int bc  = (t & 7) * 16;       // 0..112

    float acc[4][4][4];
#pragma unroll
    for (int mi = 0; mi < 4; mi++)
#pragma unroll
        for (int ni = 0; ni < 4; ni++)
#pragma unroll
            for (int q = 0; q < 4; q++) acc[mi][ni][q] = 0.0f;

    for (int k0 = 0; k0 < Kd; k0 += TBK) {
#pragma unroll
        for (int i = 0; i < 4; i++) {
            float4 v = *(const float4*)(A + (m0 + ar) * Kd + k0 + ac + i * 4);
            float4 c4 = make_float4(f2tf32(v.x), f2tf32(v.y), f2tf32(v.z), f2tf32(v.w));
            *(float4*)&As[ar][ac + i * 4] = c4;
        }
#pragma unroll
        for (int i = 0; i < 4; i++) {
            float4 v = *(const float4*)(B + (k0 + bkr) * N + n0 + bc + i * 4);
            float4 c4 = make_float4(f2tf32(v.x), f2tf32(v.y), f2tf32(v.z), f2tf32(v.w));
            *(float4*)&Bs[bkr][bc + i * 4] = c4;
        }
        __syncthreads();

#pragma unroll
        for (int kk = 0; kk < TBK / 8; kk++) {
            int kb = kk * 8;
            unsigned aR[4][4], bR[4][2];
#pragma unroll
            for (int mi = 0; mi < 4; mi++) {
                int r = wm * 64 + mi * 16 + gid;
                aR[mi][0] = __float_as_uint(As[r][kb + tig]);
                aR[mi][1] = __float_as_uint(As[r + 8][kb + tig]);
                aR[mi][2] = __float_as_uint(As[r][kb + tig + 4]);
                aR[mi][3] = __float_as_uint(As[r + 8][kb + tig + 4]);
            }
#pragma unroll
            for (int ni = 0; ni < 4; ni++) {
                int cN = wn * 32 + ni * 8 + gid;
                bR[ni][0] = __float_as_uint(Bs[kb + tig][cN]);
                bR[ni][1] = __float_as_uint(Bs[kb + tig + 4][cN]);
            }
#pragma unroll
            for (int mi = 0; mi < 4; mi++)
#pragma unroll
                for (int ni = 0; ni < 4; ni++)
                    mma_tf32(acc[mi][ni], aR[mi], bR[ni]);
        }
        __syncthreads();
    }

    // epilogue: +bias (per row), +resid, float2 stores
#pragma unroll
    for (int mi = 0; mi < 4; mi++) {
        int r0 = m0 + wm * 64 + mi * 16 + gid;
        int r1 = r0 + 8;
        float b0v = bias ? bias[r0] : 0.0f;
        float b1v = bias ? bias[r1] : 0.0f;
#pragma unroll
        for (int ni = 0; ni < 4; ni++) {
            int col = n0 + wn * 32 + ni * 8 + tig * 2;
            float2 v0, v1;
            v0.x = acc[mi][ni][0] + b0v;
            v0.y = acc[mi][ni][1] + b0v;
            v1.x = acc[mi][ni][2] + b1v;
            v1.y = acc[mi][ni][3] + b1v;
            if (resid) {
                float2 rv0 = *(const float2*)(resid + r0 * N + col);
                float2 rv1 = *(const float2*)(resid + r1 * N + col);
                v0.x += rv0.x; v0.y += rv0.y;
                v1.x += rv1.x; v1.y += rv1.y;
            }
            *(float2*)(Cout + r0 * N + col) = v0;
            *(float2*)(Cout + r1 * N + col) = v1;
        }
    }
}

// ---------------------------------------------------------------------------
// Aggregation: agg[c,p] = (sum_k2 msg[c, p+off(k2)] * affE[k2,p]) * inv[p]
// ---------------------------------------------------------------------------
#define CPT 8

__global__ void __launch_bounds__(320) agg_kernel() {
    int h  = blockIdx.x;          // 0..79
    int w  = threadIdx.x;         // 0..79
    int cy = threadIdx.y;         // 0..3
    int cbase = (blockIdx.y * 4 + cy) * CPT;

    __shared__ float saff[K2][W_];
    int tid = cy * W_ + w;
    const float* affrow = g_aff + h * W_;
    const float* invrow = g_inv + h * W_;
    for (int idx = tid; idx < K2 * W_; idx += 4 * W_) {
        int k2 = idx / W_;
        int ww = idx - k2 * W_;
        saff[k2][ww] = affrow[k2 * HW + ww] * invrow[ww];
    }
    __syncthreads();

    float acc[CPT];
#pragma unroll
    for (int cc = 0; cc < CPT; cc++) acc[cc] = 0.0f;

    const float* msgc = g_msg + cbase * HW;
    for (int i = 0; i < KS; i++) {
        int hh = h + i - 3;
        if (hh < 0 || hh >= H_) continue;
#pragma unroll
        for (int j = 0; j < KS; j++) {
            int ww = w + j - 3;
            if (ww < 0 || ww >= W_) continue;
            float a = saff[i * KS + j][w];
            const float* m = msgc + hh * W_ + ww;
#pragma unroll
            for (int cc = 0; cc < CPT; cc++)
                acc[cc] += m[cc * HW] * a;
        }
    }
#pragma unroll
    for (int cc = 0; cc < CPT; cc++)
        g_agg[(cbase + cc) * HW + h * W_ + w] = acc[cc];
}

// ---------------------------------------------------------------------------
// Launch
// ---------------------------------------------------------------------------
extern "C" void kernel_launch(void* const* d_in, const int* in_sizes, int n_in,
                              void* d_out, int out_size) {
    const float* x      = (const float*)d_in[0];
    const float* coarse = (const float*)d_in[1];
    const float* sigma  = (const float*)d_in[2];
    const float* wfeat  = (const float*)d_in[3];
    const float* wfuse  = (const float*)d_in[4];
    const float* gamma  = (const float*)d_in[5];
    const float* beta   = (const float*)d_in[6];
    const float* mean   = (const float*)d_in[7];
    const float* var    = (const float*)d_in[8];
    float* out = (float*)d_out;

    float *wp, *bias, *msg, *agg;
    cudaGetSymbolAddress((void**)&wp,   g_wp);
    cudaGetSymbolAddress((void**)&bias, g_bias);
    cudaGetSymbolAddress((void**)&msg,  g_msg);
    cudaGetSymbolAddress((void**)&agg,  g_agg);

    prep_kernel<<<C_, C_>>>(wfeat, gamma, beta, mean, var);
    affinity_kernel<<<(HW + 127) / 128, 128>>>(coarse, sigma);
    // messages = w' @ x + bias
    gemm_tc<<<dim3(HW / TBN, C_ / TBM), 256>>>(wp, x, msg, bias, nullptr);
    // spatially-varying 7x7 aggregation with softmax affinity
    agg_kernel<<<dim3(H_, C_ / (4 * CPT)), dim3(W_, 4)>>>();
    // out = x + w_fuse @ agg
    gemm_tc<<<dim3(HW / TBN, C_ / TBM), 256>>>(wfuse, agg, out, nullptr, x);
}

// round 4
// speedup vs baseline: 2.2166x; 1.1991x over previous
#include <cuda_runtime.h>
#include <math.h>

#define H_  80
#define W_  80
#define HW  6400
#define C_  256
#define CP  19
#define KS  7
#define K2  49

// Scratch (allocation-free: __device__ globals)
__device__ float g_wp[C_ * C_];     // BN-folded w_feat
__device__ float g_bias[C_];        // BN-folded bias
__device__ float g_msg[C_ * HW];    // messages
__device__ float g_agg[C_ * HW];    // aggregated
__device__ float g_aff[K2 * HW];    // unnormalized affinity exp(exp(-d/denom))
__device__ float g_inv[HW];         // 1 / sum_k2 of the above

// ---------------------------------------------------------------------------
// Fold BN into the feature conv: w'[o][c] = w[o][c]*a_c, bias[o] = sum w*b_c
// ---------------------------------------------------------------------------
__global__ void prep_kernel(const float* __restrict__ wfeat,
                            const float* __restrict__ gamma,
                            const float* __restrict__ beta,
                            const float* __restrict__ mean,
                            const float* __restrict__ var) {
    int o = blockIdx.x;
    int c = threadIdx.x;
    float a = gamma[c] * rsqrtf(var[c] + 1e-5f);
    float b = beta[c] - mean[c] * a;
    float w = wfeat[o * C_ + c];
    g_wp[o * C_ + c] = w * a;

    __shared__ float red[C_];
    red[c] = w * b;
    __syncthreads();
    for (int s = C_ / 2; s > 0; s >>= 1) {
        if (c < s) red[c] += red[c + s];
        __syncthreads();
    }
    if (c == 0) g_bias[o] = red[0];
}

// ---------------------------------------------------------------------------
// Affinity, stage 1: one block-row of taps per blockIdx.y (7x parallelism).
// Writes unnormalized e = exp(exp(-d/denom)) to g_aff.
// ---------------------------------------------------------------------------
__global__ void __launch_bounds__(128) aff_tap_kernel(
        const float* __restrict__ coarse,
        const float* __restrict__ sigma) {
    int p = blockIdx.x * 128 + threadIdx.x;   // 50*128 = 6400 exactly
    int i = blockIdx.y;                       // tap row 0..6
    int h = p / W_, w = p - h * W_;

    float sr = fmaxf(sigma[0], 0.0f);
    float invd = 1.0f / (2.0f * sr * sr + 1e-8f);

    float center[CP];
    float c2 = 0.0f;
#pragma unroll
    for (int cp = 0; cp < CP; cp++) {
        float v = coarse[cp * HW + p];
        center[cp] = v;
        c2 += v * v;   // distance when neighbor is zero-padded
    }

    int hh = h + i - 3;
    bool rowok = (hh >= 0) && (hh < H_);
    int rowbase = hh * W_;
#pragma unroll
    for (int j = 0; j < KS; j++) {
        int ww = w + j - 3;
        float d;
        if (rowok && ww >= 0 && ww < W_) {
            int q = rowbase + ww;
            d = 0.0f;
#pragma unroll
            for (int cp = 0; cp < CP; cp++) {
                float t = coarse[cp * HW + q] - center[cp];
                d += t * t;
            }
        } else {
            d = c2;
        }
        g_aff[(i * KS + j) * HW + p] = __expf(__expf(-d * invd));
    }
}

// Affinity, stage 2: normalization reciprocal.
__global__ void __launch_bounds__(128) aff_norm_kernel() {
    int p = blockIdx.x * 128 + threadIdx.x;
    float sum = 0.0f;
#pragma unroll
    for (int k = 0; k < K2; k++) sum += g_aff[k * HW + p];
    g_inv[p] = 1.0f / sum;
}

// ---------------------------------------------------------------------------
// Tensor-core GEMM (tf32 mma.sync): C[256,6400] = A[256,256] * B[256,6400]
// 128x128 block tile, BK=32, 8 warps (2x4), warp tile 64x32 (4x4 m16n8k8).
// ---------------------------------------------------------------------------
#define TBM 128
#define TBN 128
#define TBK 32

__device__ __forceinline__ float f2tf32(float x) {
    unsigned r;
    asm("cvt.rna.tf32.f32 %0, %1;" : "=r"(r) : "f"(x));
    return __uint_as_float(r);
}

__device__ __forceinline__ void mma_tf32(float* c, const unsigned* a, const unsigned* b) {
    asm volatile(
        "mma.sync.aligned.m16n8k8.row.col.f32.tf32.tf32.f32 "
        "{%0,%1,%2,%3}, {%4,%5,%6,%7}, {%8,%9}, {%0,%1,%2,%3};\n"
        : "+f"(c[0]), "+f"(c[1]), "+f"(c[2]), "+f"(c[3])
        : "r"(a[0]), "r"(a[1]), "r"(a[2]), "r"(a[3]), "r"(b[0]), "r"(b[1]));
}

__global__ void __launch_bounds__(256) gemm_tc(
        const float* __restrict__ A,      // [C_ x C_] row-major
        const float* __restrict__ B,      // [C_ x HW]
        float* __restrict__ Cout,         // [C_ x HW]
        const float* __restrict__ bias,   // may be null
        const float* __restrict__ resid) {// may be null
    const int N = HW, Kd = C_;
    __shared__ float As[TBM][TBK + 4];
    __shared__ float Bs[TBK][TBN + 8];

    int t    = threadIdx.x;
    int warp = t >> 5, lane = t & 31;
    int gid  = lane >> 2, tig = lane & 3;
    int wm   = warp >> 2, wn = warp & 3;      // 2 x 4 warps
    int m0   = blockIdx.y * TBM, n0 = blockIdx.x * TBN;

    int ar  = t >> 1;             // 0..127 (A row)
    int ac  = (t & 1) * 16;       // 0 or 16
    int bkr = t >> 3;             // 0..31  (B k-row)
    int bc  = (t & 7) * 16;       // 0..112

    float acc[4][4][4];
#pragma unroll
    for (int mi = 0; mi < 4; mi++)
#pragma unroll
        for (int ni = 0; ni < 4; ni++)
#pragma unroll
            for (int q = 0; q < 4; q++) acc[mi][ni][q] = 0.0f;

    for (int k0 = 0; k0 < Kd; k0 += TBK) {
#pragma unroll
        for (int i = 0; i < 4; i++) {
            float4 v = *(const float4*)(A + (m0 + ar) * Kd + k0 + ac + i * 4);
            float4 c4 = make_float4(f2tf32(v.x), f2tf32(v.y), f2tf32(v.z), f2tf32(v.w));
            *(float4*)&As[ar][ac + i * 4] = c4;
        }
#pragma unroll
        for (int i = 0; i < 4; i++) {
            float4 v = *(const float4*)(B + (k0 + bkr) * N + n0 + bc + i * 4);
            float4 c4 = make_float4(f2tf32(v.x), f2tf32(v.y), f2tf32(v.z), f2tf32(v.w));
            *(float4*)&Bs[bkr][bc + i * 4] = c4;
        }
        __syncthreads();

#pragma unroll
        for (int kk = 0; kk < TBK / 8; kk++) {
            int kb = kk * 8;
            unsigned aR[4][4], bR[4][2];
#pragma unroll
            for (int mi = 0; mi < 4; mi++) {
                int r = wm * 64 + mi * 16 + gid;
                aR[mi][0] = __float_as_uint(As[r][kb + tig]);
                aR[mi][1] = __float_as_uint(As[r + 8][kb + tig]);
                aR[mi][2] = __float_as_uint(As[r][kb + tig + 4]);
                aR[mi][3] = __float_as_uint(As[r + 8][kb + tig + 4]);
            }
#pragma unroll
            for (int ni = 0; ni < 4; ni++) {
                int cN = wn * 32 + ni * 8 + gid;
                bR[ni][0] = __float_as_uint(Bs[kb + tig][cN]);
                bR[ni][1] = __float_as_uint(Bs[kb + tig + 4][cN]);
            }
#pragma unroll
            for (int mi = 0; mi < 4; mi++)
#pragma unroll
                for (int ni = 0; ni < 4; ni++)
                    mma_tf32(acc[mi][ni], aR[mi], bR[ni]);
        }
        __syncthreads();
    }

#pragma unroll
    for (int mi = 0; mi < 4; mi++) {
        int r0 = m0 + wm * 64 + mi * 16 + gid;
        int r1 = r0 + 8;
        float b0v = bias ? bias[r0] : 0.0f;
        float b1v = bias ? bias[r1] : 0.0f;
#pragma unroll
        for (int ni = 0; ni < 4; ni++) {
            int col = n0 + wn * 32 + ni * 8 + tig * 2;
            float2 v0, v1;
            v0.x = acc[mi][ni][0] + b0v;
            v0.y = acc[mi][ni][1] + b0v;
            v1.x = acc[mi][ni][2] + b1v;
            v1.y = acc[mi][ni][3] + b1v;
            if (resid) {
                float2 rv0 = *(const float2*)(resid + r0 * N + col);
                float2 rv1 = *(const float2*)(resid + r1 * N + col);
                v0.x += rv0.x; v0.y += rv0.y;
                v1.x += rv1.x; v1.y += rv1.y;
            }
            *(float2*)(Cout + r0 * N + col) = v0;
            *(float2*)(Cout + r1 * N + col) = v1;
        }
    }
}

// ---------------------------------------------------------------------------
// Aggregation v2: 4 pixels x 4 channels per thread, register sliding window.
// Window [4tx-4, 4tx+8) loaded as 3 aligned float4s (edges predicated zero,
// matching zero-pad semantics). Block (20,8) = 160 threads, 32 channels.
// ---------------------------------------------------------------------------
__global__ void __launch_bounds__(160) agg_kernel() {
    int h  = blockIdx.x;                       // 0..79
    int tx = threadIdx.x;                      // 0..19 -> pixels 4tx..4tx+3
    int ty = threadIdx.y;                      // 0..7
    int cbase = (blockIdx.y * 8 + ty) * 4;     // 4 channels per thread

    __shared__ __align__(16) float saff[K2][W_];
    int tid = ty * 20 + tx;
    const float* affrow = g_aff + h * W_;
    const float* invrow = g_inv + h * W_;
    for (int idx = tid; idx < K2 * W_; idx += 160) {
        int k2 = idx / W_;
        int ww = idx - k2 * W_;
        saff[k2][ww] = affrow[k2 * HW + ww] * invrow[ww];
    }
    __syncthreads();

    float acc[4][4];   // [px][c]
#pragma unroll
    for (int px = 0; px < 4; px++)
#pragma unroll
        for (int c = 0; c < 4; c++) acc[px][c] = 0.0f;

    const float4 z4 = make_float4(0.f, 0.f, 0.f, 0.f);
    bool haveA = (tx > 0), haveC = (tx < 19);

    for (int i = 0; i < KS; i++) {
        int hh = h + i - 3;
        if (hh < 0 || hh >= H_) continue;

        // affinity row i: s[j] = saff[i*7+j][4tx .. 4tx+3]
        float4 s[KS];
#pragma unroll
        for (int j = 0; j < KS; j++)
            s[j] = *(const float4*)&saff[i * KS + j][tx * 4];

#pragma unroll
        for (int c = 0; c < 4; c++) {
            const float* mrow = g_msg + (cbase + c) * HW + hh * W_;
            float4 va = haveA ? *(const float4*)(mrow + tx * 4 - 4) : z4;
            float4 vb = *(const float4*)(mrow + tx * 4);
            float4 vc = haveC ? *(const float4*)(mrow + tx * 4 + 4) : z4;
            float win[10] = {va.y, va.z, va.w,
                             vb.x, vb.y, vb.z, vb.w,
                             vc.x, vc.y, vc.z};
#pragma unroll
            for (int j = 0; j < KS; j++) {
                acc[0][c] += win[j + 0] * s[j].x;
                acc[1][c] += win[j + 1] * s[j].y;
                acc[2][c] += win[j + 2] * s[j].z;
                acc[3][c] += win[j + 3] * s[j].w;
            }
        }
    }

#pragma unroll
    for (int c = 0; c < 4; c++) {
        float4 o = make_float4(acc[0][c], acc[1][c], acc[2][c], acc[3][c]);
        *(float4*)(g_agg + (cbase + c) * HW + h * W_ + tx * 4) = o;
    }
}

// ---------------------------------------------------------------------------
// Launch
// ---------------------------------------------------------------------------
extern "C" void kernel_launch(void* const* d_in, const int* in_sizes, int n_in,
                              void* d_out, int out_size) {
    const float* x      = (const float*)d_in[0];
    const float* coarse = (const float*)d_in[1];
    const float* sigma  = (const float*)d_in[2];
    const float* wfeat  = (const float*)d_in[3];
    const float* wfuse  = (const float*)d_in[4];
    const float* gamma  = (const float*)d_in[5];
    const float* beta   = (const float*)d_in[6];
    const float* mean   = (const float*)d_in[7];
    const float* var    = (const float*)d_in[8];
    float* out = (float*)d_out;

    float *wp, *bias, *msg, *agg;
    cudaGetSymbolAddress((void**)&wp,   g_wp);
    cudaGetSymbolAddress((void**)&bias, g_bias);
    cudaGetSymbolAddress((void**)&msg,  g_msg);
    cudaGetSymbolAddress((void**)&agg,  g_agg);

    prep_kernel<<<C_, C_>>>(wfeat, gamma, beta, mean, var);
    aff_tap_kernel<<<dim3(HW / 128, KS), 128>>>(coarse, sigma);
    aff_norm_kernel<<<HW / 128, 128>>>();
    // messages = w' @ x + bias
    gemm_tc<<<dim3(HW / TBN, C_ / TBM), 256>>>(wp, x, msg, bias, nullptr);
    // spatially-varying 7x7 aggregation with softmax affinity
    agg_kernel<<<dim3(H_, C_ / 32), dim3(20, 8)>>>();
    // out = x + w_fuse @ agg
    gemm_tc<<<dim3(HW / TBN, C_ / TBM), 256>>>(wfuse, agg, out, nullptr, x);
}

// round 5
// speedup vs baseline: 2.6250x; 1.1842x over previous
#include <cuda_runtime.h>
#include <math.h>

#define H_  80
#define W_  80
#define HW  6400
#define C_  256
#define CP  19
#define KS  7
#define K2  49

// Scratch (allocation-free: __device__ globals)
__device__ float g_wp[C_ * C_];     // BN-folded w_feat
__device__ float g_bias[C_];        // BN-folded bias
__device__ float g_msg[C_ * HW];    // messages
__device__ float g_agg[C_ * HW];    // aggregated
__device__ float g_aff[K2 * HW];    // unnormalized affinity exp(exp(-d/denom))
__device__ float g_inv[HW];         // 1 / sum_k2 of the above

// ---------------------------------------------------------------------------
// Fold BN into the feature conv: w'[o][c] = w[o][c]*a_c, bias[o] = sum w*b_c
// ---------------------------------------------------------------------------
__global__ void prep_kernel(const float* __restrict__ wfeat,
                            const float* __restrict__ gamma,
                            const float* __restrict__ beta,
                            const float* __restrict__ mean,
                            const float* __restrict__ var) {
    int o = blockIdx.x;
    int c = threadIdx.x;
    float a = gamma[c] * rsqrtf(var[c] + 1e-5f);
    float b = beta[c] - mean[c] * a;
    float w = wfeat[o * C_ + c];
    g_wp[o * C_ + c] = w * a;

    __shared__ float red[C_];
    red[c] = w * b;
    __syncthreads();
    for (int s = C_ / 2; s > 0; s >>= 1) {
        if (c < s) red[c] += red[c + s];
        __syncthreads();
    }
    if (c == 0) g_bias[o] = red[0];
}

// ---------------------------------------------------------------------------
// Affinity, stage 1: one tap-row per blockIdx.y (7x parallelism).
// ---------------------------------------------------------------------------
__global__ void __launch_bounds__(128) aff_tap_kernel(
        const float* __restrict__ coarse,
        const float* __restrict__ sigma) {
    int p = blockIdx.x * 128 + threadIdx.x;   // 50*128 = 6400 exactly
    int i = blockIdx.y;                       // tap row 0..6
    int h = p / W_, w = p - h * W_;

    float sr = fmaxf(sigma[0], 0.0f);
    float invd = 1.0f / (2.0f * sr * sr + 1e-8f);

    float center[CP];
    float c2 = 0.0f;
#pragma unroll
    for (int cp = 0; cp < CP; cp++) {
        float v = coarse[cp * HW + p];
        center[cp] = v;
        c2 += v * v;   // distance when neighbor is zero-padded
    }

    int hh = h + i - 3;
    bool rowok = (hh >= 0) && (hh < H_);
    int rowbase = hh * W_;
#pragma unroll
    for (int j = 0; j < KS; j++) {
        int ww = w + j - 3;
        float d;
        if (rowok && ww >= 0 && ww < W_) {
            int q = rowbase + ww;
            d = 0.0f;
#pragma unroll
            for (int cp = 0; cp < CP; cp++) {
                float t = coarse[cp * HW + q] - center[cp];
                d += t * t;
            }
        } else {
            d = c2;
        }
        g_aff[(i * KS + j) * HW + p] = __expf(__expf(-d * invd));
    }
}

// Affinity, stage 2: normalization reciprocal.
__global__ void __launch_bounds__(128) aff_norm_kernel() {
    int p = blockIdx.x * 128 + threadIdx.x;
    float sum = 0.0f;
#pragma unroll
    for (int k = 0; k < K2; k++) sum += g_aff[k * HW + p];
    g_inv[p] = 1.0f / sum;
}

// ---------------------------------------------------------------------------
// Tensor-core GEMM (tf32 mma.sync) with cp.async double buffering.
// C[256,6400] = A[256,256] * B[256,6400]; 64x128 tile, BK=32, 8 warps (2x4),
// warp tile 32x32 (2x4 frags of m16n8k8). Grid 50x4 = 200 blocks.
// ---------------------------------------------------------------------------
#define GBM 64
#define GBN 128
#define GBK 32
#define ASTR (GBK + 4)    // 36: frag bank = 4*gid+tig (conflict-free)
#define BSTR (GBN + 8)    // 136: frag bank = 8*tig+gid (conflict-free)

__device__ __forceinline__ void cp16(void* smem, const void* gmem) {
    unsigned s = (unsigned)__cvta_generic_to_shared(smem);
    asm volatile("cp.async.ca.shared.global [%0], [%1], 16;\n" :: "r"(s), "l"(gmem));
}

__device__ __forceinline__ void mma_tf32(float* c, const unsigned* a, const unsigned* b) {
    asm volatile(
        "mma.sync.aligned.m16n8k8.row.col.f32.tf32.tf32.f32 "
        "{%0,%1,%2,%3}, {%4,%5,%6,%7}, {%8,%9}, {%0,%1,%2,%3};\n"
        : "+f"(c[0]), "+f"(c[1]), "+f"(c[2]), "+f"(c[3])
        : "r"(a[0]), "r"(a[1]), "r"(a[2]), "r"(a[3]), "r"(b[0]), "r"(b[1]));
}

__global__ void __launch_bounds__(256) gemm_tc(
        const float* __restrict__ A,      // [C_ x C_] row-major
        const float* __restrict__ B,      // [C_ x HW]
        float* __restrict__ Cout,         // [C_ x HW]
        const float* __restrict__ bias,   // may be null
        const float* __restrict__ resid) {// may be null
    const int N = HW, Kd = C_;
    __shared__ __align__(16) float As[2][GBM][ASTR];
    __shared__ __align__(16) float Bs[2][GBK][BSTR];

    int t    = threadIdx.x;
    int warp = t >> 5, lane = t & 31;
    int gid  = lane >> 2, tig = lane & 3;
    int wm   = warp >> 2, wn = warp & 3;      // 2 x 4 warps
    int m0   = blockIdx.y * GBM, n0 = blockIdx.x * GBN;

    // cp.async tile-load indices (all 16B chunks, fully in-bounds)
    int a_row = t >> 2;              // 0..63  (A: 2 chunks/thread via row, row+?)
    // A: 512 chunks -> thread handles c = t and t+256
    // B: 1024 chunks -> c = t + 256*i, i<4

    float acc[2][4][4];
#pragma unroll
    for (int mi = 0; mi < 2; mi++)
#pragma unroll
        for (int ni = 0; ni < 4; ni++)
#pragma unroll
            for (int q = 0; q < 4; q++) acc[mi][ni][q] = 0.0f;

#define LOAD_STAGE(s, k0)                                                     \
    {                                                                          \
        _Pragma("unroll")                                                      \
        for (int i = 0; i < 2; i++) {                                          \
            int c = t + 256 * i;                                               \
            int row = c >> 3, kq = (c & 7) * 4;                                \
            cp16(&As[s][row][kq], A + (m0 + row) * Kd + (k0) + kq);            \
        }                                                                      \
        _Pragma("unroll")                                                      \
        for (int i = 0; i < 4; i++) {                                          \
            int c = t + 256 * i;                                               \
            int kr = c >> 5, cq = (c & 31) * 4;                                \
            cp16(&Bs[s][kr][cq], B + ((k0) + kr) * N + n0 + cq);               \
        }                                                                      \
        asm volatile("cp.async.commit_group;\n");                              \
    }

    LOAD_STAGE(0, 0);

    const int NIT = Kd / GBK;   // 8
    for (int it = 0; it < NIT; it++) {
        if (it + 1 < NIT) {
            LOAD_STAGE((it + 1) & 1, (it + 1) * GBK);
            asm volatile("cp.async.wait_group 1;\n");
        } else {
            asm volatile("cp.async.wait_group 0;\n");
        }
        __syncthreads();

        int s = it & 1;
#pragma unroll
        for (int kk = 0; kk < GBK / 8; kk++) {
            int kb = kk * 8;
            unsigned aR[2][4], bR[4][2];
#pragma unroll
            for (int mi = 0; mi < 2; mi++) {
                int r = wm * 32 + mi * 16 + gid;
                aR[mi][0] = __float_as_uint(As[s][r][kb + tig]);
                aR[mi][1] = __float_as_uint(As[s][r + 8][kb + tig]);
                aR[mi][2] = __float_as_uint(As[s][r][kb + tig + 4]);
                aR[mi][3] = __float_as_uint(As[s][r + 8][kb + tig + 4]);
            }
#pragma unroll
            for (int ni = 0; ni < 4; ni++) {
                int cN = wn * 32 + ni * 8 + gid;
                bR[ni][0] = __float_as_uint(Bs[s][kb + tig][cN]);
                bR[ni][1] = __float_as_uint(Bs[s][kb + tig + 4][cN]);
            }
#pragma unroll
            for (int mi = 0; mi < 2; mi++)
#pragma unroll
                for (int ni = 0; ni < 4; ni++)
                    mma_tf32(acc[mi][ni], aR[mi], bR[ni]);
        }
        __syncthreads();
    }

    // epilogue: +bias (per row), +resid, float2 stores
#pragma unroll
    for (int mi = 0; mi < 2; mi++) {
        int r0 = m0 + wm * 32 + mi * 16 + gid;
        int r1 = r0 + 8;
        float b0v = bias ? bias[r0] : 0.0f;
        float b1v = bias ? bias[r1] : 0.0f;
#pragma unroll
        for (int ni = 0; ni < 4; ni++) {
            int col = n0 + wn * 32 + ni * 8 + tig * 2;
            float2 v0, v1;
            v0.x = acc[mi][ni][0] + b0v;
            v0.y = acc[mi][ni][1] + b0v;
            v1.x = acc[mi][ni][2] + b1v;
            v1.y = acc[mi][ni][3] + b1v;
            if (resid) {
                float2 rv0 = *(const float2*)(resid + r0 * N + col);
                float2 rv1 = *(const float2*)(resid + r1 * N + col);
                v0.x += rv0.x; v0.y += rv0.y;
                v1.x += rv1.x; v1.y += rv1.y;
            }
            *(float2*)(Cout + r0 * N + col) = v0;
            *(float2*)(Cout + r1 * N + col) = v1;
        }
    }
#undef LOAD_STAGE
}

// ---------------------------------------------------------------------------
// Aggregation: 4 pixels x 4 channels per thread, register sliding window.
// ---------------------------------------------------------------------------
__global__ void __launch_bounds__(160) agg_kernel() {
    int h  = blockIdx.x;                       // 0..79
    int tx = threadIdx.x;                      // 0..19 -> pixels 4tx..4tx+3
    int ty = threadIdx.y;                      // 0..7
    int cbase = (blockIdx.y * 8 + ty) * 4;     // 4 channels per thread

    __shared__ __align__(16) float saff[K2][W_];
    int tid = ty * 20 + tx;
    const float* affrow = g_aff + h * W_;
    const float* invrow = g_inv + h * W_;
    for (int idx = tid; idx < K2 * W_; idx += 160) {
        int k2 = idx / W_;
        int ww = idx - k2 * W_;
        saff[k2][ww] = affrow[k2 * HW + ww] * invrow[ww];
    }
    __syncthreads();

    float acc[4][4];   // [px][c]
#pragma unroll
    for (int px = 0; px < 4; px++)
#pragma unroll
        for (int c = 0; c < 4; c++) acc[px][c] = 0.0f;

    const float4 z4 = make_float4(0.f, 0.f, 0.f, 0.f);
    bool haveA = (tx > 0), haveC = (tx < 19);

    for (int i = 0; i < KS; i++) {
        int hh = h + i - 3;
        if (hh < 0 || hh >= H_) continue;

        float4 s[KS];
#pragma unroll
        for (int j = 0; j < KS; j++)
            s[j] = *(const float4*)&saff[i * KS + j][tx * 4];

#pragma unroll
        for (int c = 0; c < 4; c++) {
            const float* mrow = g_msg + (cbase + c) * HW + hh * W_;
            float4 va = haveA ? *(const float4*)(mrow + tx * 4 - 4) : z4;
            float4 vb = *(const float4*)(mrow + tx * 4);
            float4 vc = haveC ? *(const float4*)(mrow + tx * 4 + 4) : z4;
            float win[10] = {va.y, va.z, va.w,
                             vb.x, vb.y, vb.z, vb.w,
                             vc.x, vc.y, vc.z};
#pragma unroll
            for (int j = 0; j < KS; j++) {
                acc[0][c] += win[j + 0] * s[j].x;
                acc[1][c] += win[j + 1] * s[j].y;
                acc[2][c] += win[j + 2] * s[j].z;
                acc[3][c] += win[j + 3] * s[j].w;
            }
        }
    }

#pragma unroll
    for (int c = 0; c < 4; c++) {
        float4 o = make_float4(acc[0][c], acc[1][c], acc[2][c], acc[3][c]);
        *(float4*)(g_agg + (cbase + c) * HW + h * W_ + tx * 4) = o;
    }
}

// ---------------------------------------------------------------------------
// Launch
// ---------------------------------------------------------------------------
extern "C" void kernel_launch(void* const* d_in, const int* in_sizes, int n_in,
                              void* d_out, int out_size) {
    const float* x      = (const float*)d_in[0];
    const float* coarse = (const float*)d_in[1];
    const float* sigma  = (const float*)d_in[2];
    const float* wfeat  = (const float*)d_in[3];
    const float* wfuse  = (const float*)d_in[4];
    const float* gamma  = (const float*)d_in[5];
    const float* beta   = (const float*)d_in[6];
    const float* mean   = (const float*)d_in[7];
    const float* var    = (const float*)d_in[8];
    float* out = (float*)d_out;

    float *wp, *bias, *msg, *agg;
    cudaGetSymbolAddress((void**)&wp,   g_wp);
    cudaGetSymbolAddress((void**)&bias, g_bias);
    cudaGetSymbolAddress((void**)&msg,  g_msg);
    cudaGetSymbolAddress((void**)&agg,  g_agg);

    prep_kernel<<<C_, C_>>>(wfeat, gamma, beta, mean, var);
    aff_tap_kernel<<<dim3(HW / 128, KS), 128>>>(coarse, sigma);
    aff_norm_kernel<<<HW / 128, 128>>>();
    // messages = w' @ x + bias
    gemm_tc<<<dim3(HW / GBN, C_ / GBM), 256>>>(wp, x, msg, bias, nullptr);
    // spatially-varying 7x7 aggregation with softmax affinity
    agg_kernel<<<dim3(H_, C_ / 32), dim3(20, 8)>>>();
    // out = x + w_fuse @ agg
    gemm_tc<<<dim3(HW / GBN, C_ / GBM), 256>>>(wfuse, agg, out, nullptr, x);
}

// round 6
// speedup vs baseline: 2.7284x; 1.0394x over previous
#include <cuda_runtime.h>
#include <math.h>

#define H_  80
#define W_  80
#define HW  6400
#define C_  256
#define CP  19
#define KS  7
#define K2  49

// Scratch (allocation-free: __device__ globals)
__device__ float g_scale[C_];       // BN per-channel scale a_c
__device__ float g_bias[C_];        // BN-folded bias for w_feat
__device__ float g_wa1[C_ * C_];    // fragment-ordered BN-folded w_feat
__device__ float g_wa2[C_ * C_];    // fragment-ordered w_fuse
__device__ float g_msg[C_ * HW];    // messages
__device__ float g_agg[C_ * HW];    // aggregated
__device__ float g_aff[K2 * HW];    // unnormalized affinity exp(exp(-d/denom))
__device__ float g_inv[HW];         // 1 / sum_k2 of the above

// ---------------------------------------------------------------------------
// prep: per-channel BN scale a_c and folded bias[o] = sum_c w[o][c]*b_c
// ---------------------------------------------------------------------------
__global__ void prep_kernel(const float* __restrict__ wfeat,
                            const float* __restrict__ gamma,
                            const float* __restrict__ beta,
                            const float* __restrict__ mean,
                            const float* __restrict__ var) {
    int o = blockIdx.x;
    int c = threadIdx.x;
    float a = gamma[c] * rsqrtf(var[c] + 1e-5f);
    float b = beta[c] - mean[c] * a;
    if (o == 0) g_scale[c] = a;

    __shared__ float red[C_];
    red[c] = wfeat[o * C_ + c] * b;
    __syncthreads();
    for (int s = C_ / 2; s > 0; s >>= 1) {
        if (c < s) red[c] += red[c + s];
        __syncthreads();
    }
    if (c == 0) g_bias[o] = red[0];
}

// ---------------------------------------------------------------------------
// arrange: weight -> fragment-ordered [kb 0..31][mb 0..15][lane][a0..a3]
// a0=(gid,tig) a1=(gid+8,tig) a2=(gid,tig+4) a3=(gid+8,tig+4) within 16x8 frag
// ---------------------------------------------------------------------------
__global__ void arrange_kernel(const float* __restrict__ src,
                               float* __restrict__ dst,
                               int use_scale) {
    int kb = blockIdx.x;          // 0..31
    int mb = blockIdx.y;          // 0..15
    int tid = threadIdx.x;        // 128
    int lane = tid & 31, q = tid >> 5;
    int gid = lane >> 2, tig = lane & 3;
    int row = mb * 16 + gid + (q & 1) * 8;
    int col = kb * 8 + tig + (q >> 1) * 4;
    float v = src[row * C_ + col];
    if (use_scale) v *= g_scale[col];
    dst[((kb * 16 + mb) * 32 + lane) * 4 + q] = v;
}

// ---------------------------------------------------------------------------
// Affinity, stage 1: one tap-row per blockIdx.y (7x parallelism).
// ---------------------------------------------------------------------------
__global__ void __launch_bounds__(128) aff_tap_kernel(
        const float* __restrict__ coarse,
        const float* __restrict__ sigma) {
    int p = blockIdx.x * 128 + threadIdx.x;   // 50*128 = 6400 exactly
    int i = blockIdx.y;                       // tap row 0..6
    int h = p / W_, w = p - h * W_;

    float sr = fmaxf(sigma[0], 0.0f);
    float invd = 1.0f / (2.0f * sr * sr + 1e-8f);

    float center[CP];
    float c2 = 0.0f;
#pragma unroll
    for (int cp = 0; cp < CP; cp++) {
        float v = coarse[cp * HW + p];
        center[cp] = v;
        c2 += v * v;   // distance when neighbor is zero-padded
    }

    int hh = h + i - 3;
    bool rowok = (hh >= 0) && (hh < H_);
    int rowbase = hh * W_;
#pragma unroll
    for (int j = 0; j < KS; j++) {
        int ww = w + j - 3;
        float d;
        if (rowok && ww >= 0 && ww < W_) {
            int q = rowbase + ww;
            d = 0.0f;
#pragma unroll
            for (int cp = 0; cp < CP; cp++) {
                float t = coarse[cp * HW + q] - center[cp];
                d += t * t;
            }
        } else {
            d = c2;
        }
        g_aff[(i * KS + j) * HW + p] = __expf(__expf(-d * invd));
    }
}

// Affinity, stage 2: normalization reciprocal.
__global__ void __launch_bounds__(128) aff_norm_kernel() {
    int p = blockIdx.x * 128 + threadIdx.x;
    float sum = 0.0f;
#pragma unroll
    for (int k = 0; k < K2; k++) sum += g_aff[k * HW + p];
    g_inv[p] = 1.0f / sum;
}

// ---------------------------------------------------------------------------
// Tensor-core GEMM (tf32 mma.sync), A-frags via LDG from arranged buffer,
// B via 3-stage cp.async. Tile 64x64, BK=32, 8 warps (2x4), warp 32x16.
// Grid 100x4 = 400 blocks.
// ---------------------------------------------------------------------------
#define GBM 64
#define GBN 64
#define GBK 32
#define BSTR (GBN + 8)    // 72: frag bank = 8*tig+gid (mod 32), conflict-free
#define NSTG 3

__device__ __forceinline__ void cp16(void* smem, const void* gmem) {
    unsigned s = (unsigned)__cvta_generic_to_shared(smem);
    asm volatile("cp.async.ca.shared.global [%0], [%1], 16;\n" :: "r"(s), "l"(gmem));
}

__device__ __forceinline__ void mma_tf32(float* c, const unsigned* a, const unsigned* b) {
    asm volatile(
        "mma.sync.aligned.m16n8k8.row.col.f32.tf32.tf32.f32 "
        "{%0,%1,%2,%3}, {%4,%5,%6,%7}, {%8,%9}, {%0,%1,%2,%3};\n"
        : "+f"(c[0]), "+f"(c[1]), "+f"(c[2]), "+f"(c[3])
        : "r"(a[0]), "r"(a[1]), "r"(a[2]), "r"(a[3]), "r"(b[0]), "r"(b[1]));
}

__global__ void __launch_bounds__(256) gemm_tc(
        const float* __restrict__ Afrag,  // fragment-ordered [32][16][32][4]
        const float* __restrict__ B,      // [C_ x HW]
        float* __restrict__ Cout,         // [C_ x HW]
        const float* __restrict__ bias,   // may be null
        const float* __restrict__ resid) {// may be null
    const int N = HW;
    __shared__ __align__(16) float Bs[NSTG][GBK][BSTR];

    int t    = threadIdx.x;
    int warp = t >> 5, lane = t & 31;
    int gid  = lane >> 2, tig = lane & 3;
    int wm   = warp >> 2, wn = warp & 3;      // 2 x 4 warps
    int m0   = blockIdx.y * GBM, n0 = blockIdx.x * GBN;
    int mb0  = blockIdx.y * 4 + wm * 2;       // 16-row block base for this warp

    // B tile: 32x64 f32 = 512 16B chunks, 2 per thread
    int kr0 = t >> 4;              // 0..15
    int co  = (t & 15) * 4;        // 0..60

    float acc[2][2][4];
#pragma unroll
    for (int mi = 0; mi < 2; mi++)
#pragma unroll
        for (int ni = 0; ni < 2; ni++)
#pragma unroll
            for (int q = 0; q < 4; q++) acc[mi][ni][q] = 0.0f;

#define LOADB(s, k0)                                                          \
    {                                                                          \
        cp16(&Bs[s][kr0][co],      B + ((k0) + kr0) * N + n0 + co);            \
        cp16(&Bs[s][kr0 + 16][co], B + ((k0) + kr0 + 16) * N + n0 + co);       \
        asm volatile("cp.async.commit_group;\n");                              \
    }

    LOADB(0, 0);
    LOADB(1, GBK);

    const int NIT = C_ / GBK;   // 8
    for (int it = 0; it < NIT; it++) {
        if (it + 1 < NIT) asm volatile("cp.async.wait_group 1;\n");
        else              asm volatile("cp.async.wait_group 0;\n");
        __syncthreads();
        if (it + 2 < NIT) LOADB((it + 2) % NSTG, (it + 2) * GBK);

        int s = it % NSTG;
#pragma unroll
        for (int kk = 0; kk < GBK / 8; kk++) {
            int kbg = it * 4 + kk;
            float4 a0 = *(const float4*)(Afrag + ((kbg * 16 + mb0) * 32 + lane) * 4);
            float4 a1 = *(const float4*)(Afrag + ((kbg * 16 + mb0 + 1) * 32 + lane) * 4);
            unsigned aR[2][4];
            aR[0][0] = __float_as_uint(a0.x); aR[0][1] = __float_as_uint(a0.y);
            aR[0][2] = __float_as_uint(a0.z); aR[0][3] = __float_as_uint(a0.w);
            aR[1][0] = __float_as_uint(a1.x); aR[1][1] = __float_as_uint(a1.y);
            aR[1][2] = __float_as_uint(a1.z); aR[1][3] = __float_as_uint(a1.w);

            unsigned bR[2][2];
#pragma unroll
            for (int ni = 0; ni < 2; ni++) {
                int cN = wn * 16 + ni * 8 + gid;
                bR[ni][0] = __float_as_uint(Bs[s][kk * 8 + tig][cN]);
                bR[ni][1] = __float_as_uint(Bs[s][kk * 8 + tig + 4][cN]);
            }
#pragma unroll
            for (int mi = 0; mi < 2; mi++)
#pragma unroll
                for (int ni = 0; ni < 2; ni++)
                    mma_tf32(acc[mi][ni], aR[mi], bR[ni]);
        }
        __syncthreads();
    }

    // epilogue: +bias (per row), +resid, float2 stores
#pragma unroll
    for (int mi = 0; mi < 2; mi++) {
        int r0 = m0 + wm * 32 + mi * 16 + gid;
        int r1 = r0 + 8;
        float b0v = bias ? bias[r0] : 0.0f;
        float b1v = bias ? bias[r1] : 0.0f;
#pragma unroll
        for (int ni = 0; ni < 2; ni++) {
            int col = n0 + wn * 16 + ni * 8 + tig * 2;
            float2 v0, v1;
            v0.x = acc[mi][ni][0] + b0v;
            v0.y = acc[mi][ni][1] + b0v;
            v1.x = acc[mi][ni][2] + b1v;
            v1.y = acc[mi][ni][3] + b1v;
            if (resid) {
                float2 rv0 = *(const float2*)(resid + r0 * N + col);
                float2 rv1 = *(const float2*)(resid + r1 * N + col);
                v0.x += rv0.x; v0.y += rv0.y;
                v1.x += rv1.x; v1.y += rv1.y;
            }
            *(float2*)(Cout + r0 * N + col) = v0;
            *(float2*)(Cout + r1 * N + col) = v1;
        }
    }
#undef LOADB
}

// ---------------------------------------------------------------------------
// Aggregation: 4 pixels x 4 channels per thread, register sliding window.
// ---------------------------------------------------------------------------
__global__ void __launch_bounds__(160) agg_kernel() {
    int h  = blockIdx.x;                       // 0..79
    int tx = threadIdx.x;                      // 0..19 -> pixels 4tx..4tx+3
    int ty = threadIdx.y;                      // 0..7
    int cbase = (blockIdx.y * 8 + ty) * 4;     // 4 channels per thread

    __shared__ __align__(16) float saff[K2][W_];
    int tid = ty * 20 + tx;
    const float* affrow = g_aff + h * W_;
    const float* invrow = g_inv + h * W_;
    for (int idx = tid; idx < K2 * W_; idx += 160) {
        int k2 = idx / W_;
        int ww = idx - k2 * W_;
        saff[k2][ww] = affrow[k2 * HW + ww] * invrow[ww];
    }
    __syncthreads();

    float acc[4][4];   // [px][c]
#pragma unroll
    for (int px = 0; px < 4; px++)
#pragma unroll
        for (int c = 0; c < 4; c++) acc[px][c] = 0.0f;

    const float4 z4 = make_float4(0.f, 0.f, 0.f, 0.f);
    bool haveA = (tx > 0), haveC = (tx < 19);

    for (int i = 0; i < KS; i++) {
        int hh = h + i - 3;
        if (hh < 0 || hh >= H_) continue;

        float4 s[KS];
#pragma unroll
        for (int j = 0; j < KS; j++)
            s[j] = *(const float4*)&saff[i * KS + j][tx * 4];

#pragma unroll
        for (int c = 0; c < 4; c++) {
            const float* mrow = g_msg + (cbase + c) * HW + hh * W_;
            float4 va = haveA ? *(const float4*)(mrow + tx * 4 - 4) : z4;
            float4 vb = *(const float4*)(mrow + tx * 4);
            float4 vc = haveC ? *(const float4*)(mrow + tx * 4 + 4) : z4;
            float win[10] = {va.y, va.z, va.w,
                             vb.x, vb.y, vb.z, vb.w,
                             vc.x, vc.y, vc.z};
#pragma unroll
            for (int j = 0; j < KS; j++) {
                acc[0][c] += win[j + 0] * s[j].x;
                acc[1][c] += win[j + 1] * s[j].y;
                acc[2][c] += win[j + 2] * s[j].z;
                acc[3][c] += win[j + 3] * s[j].w;
            }
        }
    }

#pragma unroll
    for (int c = 0; c < 4; c++) {
        float4 o = make_float4(acc[0][c], acc[1][c], acc[2][c], acc[3][c]);
        *(float4*)(g_agg + (cbase + c) * HW + h * W_ + tx * 4) = o;
    }
}

// ---------------------------------------------------------------------------
// Launch
// ---------------------------------------------------------------------------
extern "C" void kernel_launch(void* const* d_in, const int* in_sizes, int n_in,
                              void* d_out, int out_size) {
    const float* x      = (const float*)d_in[0];
    const float* coarse = (const float*)d_in[1];
    const float* sigma  = (const float*)d_in[2];
    const float* wfeat  = (const float*)d_in[3];
    const float* wfuse  = (const float*)d_in[4];
    const float* gamma  = (const float*)d_in[5];
    const float* beta   = (const float*)d_in[6];
    const float* mean   = (const float*)d_in[7];
    const float* var    = (const float*)d_in[8];
    float* out = (float*)d_out;

    float *wa1, *wa2, *bias, *msg, *agg;
    cudaGetSymbolAddress((void**)&wa1,  g_wa1);
    cudaGetSymbolAddress((void**)&wa2,  g_wa2);
    cudaGetSymbolAddress((void**)&bias, g_bias);
    cudaGetSymbolAddress((void**)&msg,  g_msg);
    cudaGetSymbolAddress((void**)&agg,  g_agg);

    prep_kernel<<<C_, C_>>>(wfeat, gamma, beta, mean, var);
    arrange_kernel<<<dim3(C_ / 8, C_ / 16), 128>>>(wfeat, wa1, 1);
    arrange_kernel<<<dim3(C_ / 8, C_ / 16), 128>>>(wfuse, wa2, 0);
    aff_tap_kernel<<<dim3(HW / 128, KS), 128>>>(coarse, sigma);
    aff_norm_kernel<<<HW / 128, 128>>>();
    // messages = w' @ x + bias
    gemm_tc<<<dim3(HW / GBN, C_ / GBM), 256>>>(wa1, x, msg, bias, nullptr);
    // spatially-varying 7x7 aggregation with softmax affinity
    agg_kernel<<<dim3(H_, C_ / 32), dim3(20, 8)>>>();
    // out = x + w_fuse @ agg
    gemm_tc<<<dim3(HW / GBN, C_ / GBM), 256>>>(wa2, agg, out, nullptr, x);
}

// round 7
// speedup vs baseline: 2.9778x; 1.0914x over previous
#include <cuda_runtime.h>
#include <math.h>

#define H_  80
#define W_  80
#define HW  6400
#define C_  256
#define CP  19
#define KS  7
#define K2  49

// Scratch (allocation-free: __device__ globals)
__device__ float g_bias[C_];        // BN-folded bias for w_feat
__device__ float g_wa1[C_ * C_];    // fragment-ordered BN-folded w_feat
__device__ float g_wa2[C_ * C_];    // fragment-ordered w_fuse
__device__ float g_msg[C_ * HW];    // messages
__device__ float g_agg[C_ * HW];    // aggregated
__device__ float g_aff[K2 * HW];    // unnormalized affinity exp(exp(-d/denom))

// ---------------------------------------------------------------------------
// setup: one launch doing (a) both weight rearrangements (BN scale folded
// into w_feat) and (b) the BN-folded bias reduction. Partitioned by blockIdx.
// Fragment order: [kb 0..31][mb 0..15][lane][a0..a3],
// a0=(gid,tig) a1=(gid+8,tig) a2=(gid,tig+4) a3=(gid+8,tig+4) in 16x8 frag.
// ---------------------------------------------------------------------------
__global__ void __launch_bounds__(128) setup_kernel(
        const float* __restrict__ wfeat, const float* __restrict__ wfuse,
        const float* __restrict__ gamma, const float* __restrict__ beta,
        const float* __restrict__ mean,  const float* __restrict__ var) {
    int b = blockIdx.x;
    int t = threadIdx.x;
    if (b < 1024) {
        int w2 = b >> 9;              // 0: wfeat (scaled), 1: wfuse
        int bb = b & 511;
        int kb = bb & 31, mb = bb >> 5;
        int lane = t & 31, q = t >> 5;
        int gid = lane >> 2, tig = lane & 3;
        int row = mb * 16 + gid + (q & 1) * 8;
        int col = kb * 8 + tig + (q >> 1) * 4;
        const float* src = w2 ? wfuse : wfeat;
        float v = src[row * C_ + col];
        if (!w2) v *= gamma[col] * rsqrtf(var[col] + 1e-5f);
        float* dst = w2 ? g_wa2 : g_wa1;
        dst[((kb * 16 + mb) * 32 + lane) * 4 + q] = v;
    } else {
        int o = b - 1024;             // 0..255
        float s = 0.0f;
        for (int c = t; c < C_; c += 128) {
            float a = gamma[c] * rsqrtf(var[c] + 1e-5f);
            s += wfeat[o * C_ + c] * (beta[c] - mean[c] * a);
        }
#pragma unroll
        for (int off = 16; off; off >>= 1) s += __shfl_xor_sync(~0u, s, off);
        __shared__ float red[4];
        if ((t & 31) == 0) red[t >> 5] = s;
        __syncthreads();
        if (t == 0) g_bias[o] = red[0] + red[1] + red[2] + red[3];
    }
}

// ---------------------------------------------------------------------------
// Affinity: 2 pixels per thread, sliding window over j, zero-pad uniformity
// ((0-center)^2 = center^2 reproduces the padded-distance exactly).
// Block (40,4) = 160 thr; grid (20, 7): blockIdx.y = tap row i.
// ---------------------------------------------------------------------------
__global__ void __launch_bounds__(160) aff_tap_kernel(
        const float* __restrict__ coarse,
        const float* __restrict__ sigma) {
    int tx = threadIdx.x;            // 0..39 -> pixels 2tx, 2tx+1
    int h  = blockIdx.x * 4 + threadIdx.y;
    int i  = blockIdx.y;             // tap row 0..6
    int b0 = tx * 2;

    float sr = fmaxf(sigma[0], 0.0f);
    float invd = 1.0f / (2.0f * sr * sr + 1e-8f);

    int hh = h + i - 3;
    bool rowok = (hh >= 0) && (hh < H_);
    const float* crow = coarse + h * W_;
    const float* nrow = coarse + (rowok ? hh : 0) * W_;

    bool v[5];
#pragma unroll
    for (int l = 0; l < 5; l++) {
        int col = b0 - 4 + 2 * l;
        v[l] = rowok && (col >= 0) && (col <= W_ - 2);
    }

    float d[KS][2];
#pragma unroll
    for (int j = 0; j < KS; j++) { d[j][0] = 0.0f; d[j][1] = 0.0f; }

    const float2 z2 = make_float2(0.0f, 0.0f);
#pragma unroll
    for (int cp = 0; cp < CP; cp++) {
        float2 cen = *(const float2*)(crow + cp * HW + b0);
        const float* nb = nrow + cp * HW;
        float win[8];
        float2 L;
        L = v[0] ? *(const float2*)(nb + b0 - 4) : z2; win[0] = L.y;
        L = v[1] ? *(const float2*)(nb + b0 - 2) : z2; win[1] = L.x; win[2] = L.y;
        L = v[2] ? *(const float2*)(nb + b0)     : z2; win[3] = L.x; win[4] = L.y;
        L = v[3] ? *(const float2*)(nb + b0 + 2) : z2; win[5] = L.x; win[6] = L.y;
        L = v[4] ? *(const float2*)(nb + b0 + 4) : z2; win[7] = L.x;
#pragma unroll
        for (int j = 0; j < KS; j++) {
            float t0 = win[j]     - cen.x; d[j][0] += t0 * t0;
            float t1 = win[j + 1] - cen.y; d[j][1] += t1 * t1;
        }
    }

    int p = h * W_ + b0;
#pragma unroll
    for (int j = 0; j < KS; j++) {
        g_aff[(i * KS + j) * HW + p]     = __expf(__expf(-d[j][0] * invd));
        g_aff[(i * KS + j) * HW + p + 1] = __expf(__expf(-d[j][1] * invd));
    }
}

// ---------------------------------------------------------------------------
// Tensor-core GEMM (tf32 mma.sync), A-frags via LDG from arranged buffer,
// B via 3-stage cp.async. Tile 64x64, BK=32, 8 warps (2x4), warp 32x16.
// ---------------------------------------------------------------------------
#define GBM 64
#define GBN 64
#define GBK 32
#define BSTR (GBN + 8)    // 72: frag bank = 8*tig+gid (mod 32), conflict-free
#define NSTG 3

__device__ __forceinline__ void cp16(void* smem, const void* gmem) {
    unsigned s = (unsigned)__cvta_generic_to_shared(smem);
    asm volatile("cp.async.ca.shared.global [%0], [%1], 16;\n" :: "r"(s), "l"(gmem));
}

__device__ __forceinline__ void mma_tf32(float* c, const unsigned* a, const unsigned* b) {
    asm volatile(
        "mma.sync.aligned.m16n8k8.row.col.f32.tf32.tf32.f32 "
        "{%0,%1,%2,%3}, {%4,%5,%6,%7}, {%8,%9}, {%0,%1,%2,%3};\n"
        : "+f"(c[0]), "+f"(c[1]), "+f"(c[2]), "+f"(c[3])
        : "r"(a[0]), "r"(a[1]), "r"(a[2]), "r"(a[3]), "r"(b[0]), "r"(b[1]));
}

__global__ void __launch_bounds__(256) gemm_tc(
        const float* __restrict__ Afrag,  // fragment-ordered [32][16][32][4]
        const float* __restrict__ B,      // [C_ x HW]
        float* __restrict__ Cout,         // [C_ x HW]
        const float* __restrict__ bias,   // may be null
        const float* __restrict__ resid) {// may be null
    const int N = HW;
    __shared__ __align__(16) float Bs[NSTG][GBK][BSTR];

    int t    = threadIdx.x;
    int warp = t >> 5, lane = t & 31;
    int gid  = lane >> 2, tig = lane & 3;
    int wm   = warp >> 2, wn = warp & 3;      // 2 x 4 warps
    int m0   = blockIdx.y * GBM, n0 = blockIdx.x * GBN;
    int mb0  = blockIdx.y * 4 + wm * 2;       // 16-row block base for this warp

    int kr0 = t >> 4;              // 0..15
    int co  = (t & 15) * 4;        // 0..60

    float acc[2][2][4];
#pragma unroll
    for (int mi = 0; mi < 2; mi++)
#pragma unroll
        for (int ni = 0; ni < 2; ni++)
#pragma unroll
            for (int q = 0; q < 4; q++) acc[mi][ni][q] = 0.0f;

#define LOADB(s, k0)                                                          \
    {                                                                          \
        cp16(&Bs[s][kr0][co],      B + ((k0) + kr0) * N + n0 + co);            \
        cp16(&Bs[s][kr0 + 16][co], B + ((k0) + kr0 + 16) * N + n0 + co);       \
        asm volatile("cp.async.commit_group;\n");                              \
    }

    LOADB(0, 0);
    LOADB(1, GBK);

    const int NIT = C_ / GBK;   // 8
    for (int it = 0; it < NIT; it++) {
        if (it + 1 < NIT) asm volatile("cp.async.wait_group 1;\n");
        else              asm volatile("cp.async.wait_group 0;\n");
        __syncthreads();
        if (it + 2 < NIT) LOADB((it + 2) % NSTG, (it + 2) * GBK);

        int s = it % NSTG;
#pragma unroll
        for (int kk = 0; kk < GBK / 8; kk++) {
            int kbg = it * 4 + kk;
            float4 a0 = *(const float4*)(Afrag + ((kbg * 16 + mb0) * 32 + lane) * 4);
            float4 a1 = *(const float4*)(Afrag + ((kbg * 16 + mb0 + 1) * 32 + lane) * 4);
            unsigned aR[2][4];
            aR[0][0] = __float_as_uint(a0.x); aR[0][1] = __float_as_uint(a0.y);
            aR[0][2] = __float_as_uint(a0.z); aR[0][3] = __float_as_uint(a0.w);
            aR[1][0] = __float_as_uint(a1.x); aR[1][1] = __float_as_uint(a1.y);
            aR[1][2] = __float_as_uint(a1.z); aR[1][3] = __float_as_uint(a1.w);

            unsigned bR[2][2];
#pragma unroll
            for (int ni = 0; ni < 2; ni++) {
                int cN = wn * 16 + ni * 8 + gid;
                bR[ni][0] = __float_as_uint(Bs[s][kk * 8 + tig][cN]);
                bR[ni][1] = __float_as_uint(Bs[s][kk * 8 + tig + 4][cN]);
            }
#pragma unroll
            for (int mi = 0; mi < 2; mi++)
#pragma unroll
                for (int ni = 0; ni < 2; ni++)
                    mma_tf32(acc[mi][ni], aR[mi], bR[ni]);
        }
        __syncthreads();
    }

#pragma unroll
    for (int mi = 0; mi < 2; mi++) {
        int r0 = m0 + wm * 32 + mi * 16 + gid;
        int r1 = r0 + 8;
        float b0v = bias ? bias[r0] : 0.0f;
        float b1v = bias ? bias[r1] : 0.0f;
#pragma unroll
        for (int ni = 0; ni < 2; ni++) {
            int col = n0 + wn * 16 + ni * 8 + tig * 2;
            float2 v0, v1;
            v0.x = acc[mi][ni][0] + b0v;
            v0.y = acc[mi][ni][1] + b0v;
            v1.x = acc[mi][ni][2] + b1v;
            v1.y = acc[mi][ni][3] + b1v;
            if (resid) {
                float2 rv0 = *(const float2*)(resid + r0 * N + col);
                float2 rv1 = *(const float2*)(resid + r1 * N + col);
                v0.x += rv0.x; v0.y += rv0.y;
                v1.x += rv1.x; v1.y += rv1.y;
            }
            *(float2*)(Cout + r0 * N + col) = v0;
            *(float2*)(Cout + r1 * N + col) = v1;
        }
    }
#undef LOADB
}

// ---------------------------------------------------------------------------
// Aggregation: 4 pixels x 4 channels per thread, register sliding window.
// Softmax normalization fused: per-pixel tap-sum computed from smem here.
// ---------------------------------------------------------------------------
__global__ void __launch_bounds__(160) agg_kernel() {
    int h  = blockIdx.x;                       // 0..79
    int tx = threadIdx.x;                      // 0..19 -> pixels 4tx..4tx+3
    int ty = threadIdx.y;                      // 0..7
    int cbase = (blockIdx.y * 8 + ty) * 4;     // 4 channels per thread

    __shared__ __align__(16) float saff[K2][W_];
    __shared__ __align__(16) float sinv[W_];
    int tid = ty * 20 + tx;
    const float* affrow = g_aff + h * W_;
    for (int idx = tid; idx < K2 * W_; idx += 160) {
        int k2 = idx / W_;
        int ww = idx - k2 * W_;
        saff[k2][ww] = affrow[k2 * HW + ww];
    }
    __syncthreads();
    if (tid < W_) {
        float s = 0.0f;
#pragma unroll
        for (int k = 0; k < K2; k++) s += saff[k][tid];
        sinv[tid] = 1.0f / s;
    }
    __syncthreads();

    float acc[4][4];   // [px][c]
#pragma unroll
    for (int px = 0; px < 4; px++)
#pragma unroll
        for (int c = 0; c < 4; c++) acc[px][c] = 0.0f;

    const float4 z4 = make_float4(0.f, 0.f, 0.f, 0.f);
    bool haveA = (tx > 0), haveC = (tx < 19);

    for (int i = 0; i < KS; i++) {
        int hh = h + i - 3;
        if (hh < 0 || hh >= H_) continue;

        float4 s[KS];
#pragma unroll
        for (int j = 0; j < KS; j++)
            s[j] = *(const float4*)&saff[i * KS + j][tx * 4];

#pragma unroll
        for (int c = 0; c < 4; c++) {
            const float* mrow = g_msg + (cbase + c) * HW + hh * W_;
            float4 va = haveA ? *(const float4*)(mrow + tx * 4 - 4) : z4;
            float4 vb = *(const float4*)(mrow + tx * 4);
            float4 vc = haveC ? *(const float4*)(mrow + tx * 4 + 4) : z4;
            float win[10] = {va.y, va.z, va.w,
                             vb.x, vb.y, vb.z, vb.w,
                             vc.x, vc.y, vc.z};
#pragma unroll
            for (int j = 0; j < KS; j++) {
                acc[0][c] += win[j + 0] * s[j].x;
                acc[1][c] += win[j + 1] * s[j].y;
                acc[2][c] += win[j + 2] * s[j].z;
                acc[3][c] += win[j + 3] * s[j].w;
            }
        }
    }

    float4 si = *(const float4*)&sinv[tx * 4];
#pragma unroll
    for (int c = 0; c < 4; c++) {
        float4 o = make_float4(acc[0][c] * si.x, acc[1][c] * si.y,
                               acc[2][c] * si.z, acc[3][c] * si.w);
        *(float4*)(g_agg + (cbase + c) * HW + h * W_ + tx * 4) = o;
    }
}

// ---------------------------------------------------------------------------
// Launch
// ---------------------------------------------------------------------------
extern "C" void kernel_launch(void* const* d_in, const int* in_sizes, int n_in,
                              void* d_out, int out_size) {
    const float* x      = (const float*)d_in[0];
    const float* coarse = (const float*)d_in[1];
    const float* sigma  = (const float*)d_in[2];
    const float* wfeat  = (const float*)d_in[3];
    const float* wfuse  = (const float*)d_in[4];
    const float* gamma  = (const float*)d_in[5];
    const float* beta   = (const float*)d_in[6];
    const float* mean   = (const float*)d_in[7];
    const float* var    = (const float*)d_in[8];
    float* out = (float*)d_out;

    float *wa1, *wa2, *bias, *msg, *agg;
    cudaGetSymbolAddress((void**)&wa1,  g_wa1);
    cudaGetSymbolAddress((void**)&wa2,  g_wa2);
    cudaGetSymbolAddress((void**)&bias, g_bias);
    cudaGetSymbolAddress((void**)&msg,  g_msg);
    cudaGetSymbolAddress((void**)&agg,  g_agg);

    setup_kernel<<<1280, 128>>>(wfeat, wfuse, gamma, beta, mean, var);
    aff_tap_kernel<<<dim3(H_ / 4, KS), dim3(40, 4)>>>(coarse, sigma);
    // messages = w' @ x + bias
    gemm_tc<<<dim3(HW / GBN, C_ / GBM), 256>>>(wa1, x, msg, bias, nullptr);
    // spatially-varying 7x7 aggregation with fused softmax normalization
    agg_kernel<<<dim3(H_, C_ / 32), dim3(20, 8)>>>();
    // out = x + w_fuse @ agg
    gemm_tc<<<dim3(HW / GBN, C_ / GBM), 256>>>(wa2, agg, out, nullptr, x);
}

// round 8
// speedup vs baseline: 3.1878x; 1.0705x over previous
#include <cuda_runtime.h>
#include <cuda_bf16.h>
#include <math.h>

#define H_  80
#define W_  80
#define HW  6400
#define C_  256
#define CP  19
#define KS  7
#define K2  49

// Scratch (allocation-free: __device__ globals)
__device__ float g_bias[C_];           // BN-folded bias for w_feat
__device__ float g_wa1[C_ * C_];       // fragment-ordered BN-folded w_feat
__device__ float g_wa2[C_ * C_];       // fragment-ordered w_fuse
__device__ unsigned g_msgpk[128 * HW]; // messages, bf16x2 channel pairs
__device__ float g_agg[C_ * HW];       // aggregated (fp32)
__device__ float g_aff[K2 * HW];       // unnormalized affinity exp(exp(-d/denom))

// ---------------------------------------------------------------------------
// setup: both weight rearrangements (BN scale folded into w_feat) + bias.
// Fragment order: [kb 0..31][mb 0..15][lane][a0..a3].
// ---------------------------------------------------------------------------
__global__ void __launch_bounds__(128) setup_kernel(
        const float* __restrict__ wfeat, const float* __restrict__ wfuse,
        const float* __restrict__ gamma, const float* __restrict__ beta,
        const float* __restrict__ mean,  const float* __restrict__ var) {
    int b = blockIdx.x;
    int t = threadIdx.x;
    if (b < 1024) {
        int w2 = b >> 9;              // 0: wfeat (scaled), 1: wfuse
        int bb = b & 511;
        int kb = bb & 31, mb = bb >> 5;
        int lane = t & 31, q = t >> 5;
        int gid = lane >> 2, tig = lane & 3;
        int row = mb * 16 + gid + (q & 1) * 8;
        int col = kb * 8 + tig + (q >> 1) * 4;
        const float* src = w2 ? wfuse : wfeat;
        float v = src[row * C_ + col];
        if (!w2) v *= gamma[col] * rsqrtf(var[col] + 1e-5f);
        float* dst = w2 ? g_wa2 : g_wa1;
        dst[((kb * 16 + mb) * 32 + lane) * 4 + q] = v;
    } else {
        int o = b - 1024;             // 0..255
        float s = 0.0f;
        for (int c = t; c < C_; c += 128) {
            float a = gamma[c] * rsqrtf(var[c] + 1e-5f);
            s += wfeat[o * C_ + c] * (beta[c] - mean[c] * a);
        }
#pragma unroll
        for (int off = 16; off; off >>= 1) s += __shfl_xor_sync(~0u, s, off);
        __shared__ float red[4];
        if ((t & 31) == 0) red[t >> 5] = s;
        __syncthreads();
        if (t == 0) g_bias[o] = red[0] + red[1] + red[2] + red[3];
    }
}

// ---------------------------------------------------------------------------
// Affinity: 2 pixels per thread, sliding window, zero-pad uniformity.
// ---------------------------------------------------------------------------
__global__ void __launch_bounds__(160) aff_tap_kernel(
        const float* __restrict__ coarse,
        const float* __restrict__ sigma) {
    int tx = threadIdx.x;            // 0..39 -> pixels 2tx, 2tx+1
    int h  = blockIdx.x * 4 + threadIdx.y;
    int i  = blockIdx.y;             // tap row 0..6
    int b0 = tx * 2;

    float sr = fmaxf(sigma[0], 0.0f);
    float invd = 1.0f / (2.0f * sr * sr + 1e-8f);

    int hh = h + i - 3;
    bool rowok = (hh >= 0) && (hh < H_);
    const float* crow = coarse + h * W_;
    const float* nrow = coarse + (rowok ? hh : 0) * W_;

    bool v[5];
#pragma unroll
    for (int l = 0; l < 5; l++) {
        int col = b0 - 4 + 2 * l;
        v[l] = rowok && (col >= 0) && (col <= W_ - 2);
    }

    float d[KS][2];
#pragma unroll
    for (int j = 0; j < KS; j++) { d[j][0] = 0.0f; d[j][1] = 0.0f; }

    const float2 z2 = make_float2(0.0f, 0.0f);
#pragma unroll
    for (int cp = 0; cp < CP; cp++) {
        float2 cen = *(const float2*)(crow + cp * HW + b0);
        const float* nb = nrow + cp * HW;
        float win[8];
        float2 L;
        L = v[0] ? *(const float2*)(nb + b0 - 4) : z2; win[0] = L.y;
        L = v[1] ? *(const float2*)(nb + b0 - 2) : z2; win[1] = L.x; win[2] = L.y;
        L = v[2] ? *(const float2*)(nb + b0)     : z2; win[3] = L.x; win[4] = L.y;
        L = v[3] ? *(const float2*)(nb + b0 + 2) : z2; win[5] = L.x; win[6] = L.y;
        L = v[4] ? *(const float2*)(nb + b0 + 4) : z2; win[7] = L.x;
#pragma unroll
        for (int j = 0; j < KS; j++) {
            float t0 = win[j]     - cen.x; d[j][0] += t0 * t0;
            float t1 = win[j + 1] - cen.y; d[j][1] += t1 * t1;
        }
    }

    int p = h * W_ + b0;
#pragma unroll
    for (int j = 0; j < KS; j++) {
        g_aff[(i * KS + j) * HW + p]     = __expf(__expf(-d[j][0] * invd));
        g_aff[(i * KS + j) * HW + p + 1] = __expf(__expf(-d[j][1] * invd));
    }
}

// ---------------------------------------------------------------------------
// Tensor-core GEMM (tf32 mma.sync), A-frags via LDG from arranged buffer,
// B via 3-stage cp.async. Tile 64x64, BK=32, 8 warps (2x4), warp 32x16.
// Epilogue: if msgpk != null, emit bf16x2 channel-pairs (rows r, r+8);
// else fp32 (+resid).
// ---------------------------------------------------------------------------
#define GBM 64
#define GBN 64
#define GBK 32
#define BSTR (GBN + 8)
#define NSTG 3

__device__ __forceinline__ void cp16(void* smem, const void* gmem) {
    unsigned s = (unsigned)__cvta_generic_to_shared(smem);
    asm volatile("cp.async.ca.shared.global [%0], [%1], 16;\n" :: "r"(s), "l"(gmem));
}

__device__ __forceinline__ void mma_tf32(float* c, const unsigned* a, const unsigned* b) {
    asm volatile(
        "mma.sync.aligned.m16n8k8.row.col.f32.tf32.tf32.f32 "
        "{%0,%1,%2,%3}, {%4,%5,%6,%7}, {%8,%9}, {%0,%1,%2,%3};\n"
        : "+f"(c[0]), "+f"(c[1]), "+f"(c[2]), "+f"(c[3])
        : "r"(a[0]), "r"(a[1]), "r"(a[2]), "r"(a[3]), "r"(b[0]), "r"(b[1]));
}

__global__ void __launch_bounds__(256) gemm_tc(
        const float* __restrict__ Afrag,
        const float* __restrict__ B,
        float* __restrict__ Cout,          // used when msgpk == null
        unsigned* __restrict__ msgpk,      // packed output (or null)
        const float* __restrict__ bias,
        const float* __restrict__ resid) {
    const int N = HW;
    __shared__ __align__(16) float Bs[NSTG][GBK][BSTR];

    int t    = threadIdx.x;
    int warp = t >> 5, lane = t & 31;
    int gid  = lane >> 2, tig = lane & 3;
    int wm   = warp >> 2, wn = warp & 3;
    int m0   = blockIdx.y * GBM, n0 = blockIdx.x * GBN;
    int mb0  = blockIdx.y * 4 + wm * 2;

    int kr0 = t >> 4;
    int co  = (t & 15) * 4;

    float acc[2][2][4];
#pragma unroll
    for (int mi = 0; mi < 2; mi++)
#pragma unroll
        for (int ni = 0; ni < 2; ni++)
#pragma unroll
            for (int q = 0; q < 4; q++) acc[mi][ni][q] = 0.0f;

#define LOADB(s, k0)                                                          \
    {                                                                          \
        cp16(&Bs[s][kr0][co],      B + ((k0) + kr0) * N + n0 + co);            \
        cp16(&Bs[s][kr0 + 16][co], B + ((k0) + kr0 + 16) * N + n0 + co);       \
        asm volatile("cp.async.commit_group;\n");                              \
    }

    LOADB(0, 0);
    LOADB(1, GBK);

    const int NIT = C_ / GBK;   // 8
    for (int it = 0; it < NIT; it++) {
        if (it + 1 < NIT) asm volatile("cp.async.wait_group 1;\n");
        else              asm volatile("cp.async.wait_group 0;\n");
        __syncthreads();
        if (it + 2 < NIT) LOADB((it + 2) % NSTG, (it + 2) * GBK);

        int s = it % NSTG;
#pragma unroll
        for (int kk = 0; kk < GBK / 8; kk++) {
            int kbg = it * 4 + kk;
            float4 a0 = *(const float4*)(Afrag + ((kbg * 16 + mb0) * 32 + lane) * 4);
            float4 a1 = *(const float4*)(Afrag + ((kbg * 16 + mb0 + 1) * 32 + lane) * 4);
            unsigned aR[2][4];
            aR[0][0] = __float_as_uint(a0.x); aR[0][1] = __float_as_uint(a0.y);
            aR[0][2] = __float_as_uint(a0.z); aR[0][3] = __float_as_uint(a0.w);
            aR[1][0] = __float_as_uint(a1.x); aR[1][1] = __float_as_uint(a1.y);
            aR[1][2] = __float_as_uint(a1.z); aR[1][3] = __float_as_uint(a1.w);

            unsigned bR[2][2];
#pragma unroll
            for (int ni = 0; ni < 2; ni++) {
                int cN = wn * 16 + ni * 8 + gid;
                bR[ni][0] = __float_as_uint(Bs[s][kk * 8 + tig][cN]);
                bR[ni][1] = __float_as_uint(Bs[s][kk * 8 + tig + 4][cN]);
            }
#pragma unroll
            for (int mi = 0; mi < 2; mi++)
#pragma unroll
                for (int ni = 0; ni < 2; ni++)
                    mma_tf32(acc[mi][ni], aR[mi], bR[ni]);
        }
        __syncthreads();
    }

#pragma unroll
    for (int mi = 0; mi < 2; mi++) {
        int r0 = m0 + wm * 32 + mi * 16 + gid;
        int r1 = r0 + 8;
        float b0v = bias ? bias[r0] : 0.0f;
        float b1v = bias ? bias[r1] : 0.0f;
#pragma unroll
        for (int ni = 0; ni < 2; ni++) {
            int col = n0 + wn * 16 + ni * 8 + tig * 2;
            float2 v0, v1;
            v0.x = acc[mi][ni][0] + b0v;
            v0.y = acc[mi][ni][1] + b0v;
            v1.x = acc[mi][ni][2] + b1v;
            v1.y = acc[mi][ni][3] + b1v;
            if (msgpk) {
                // pair id: rows (r0, r0+8) -> pid = (r0>>4)*8 + gid
                int pid = ((m0 >> 4) + wm * 2 + mi) * 8 + gid;
                __nv_bfloat162 w0 = __floats2bfloat162_rn(v0.x, v1.x);
                __nv_bfloat162 w1 = __floats2bfloat162_rn(v0.y, v1.y);
                uint2 pk;
                pk.x = *reinterpret_cast<unsigned*>(&w0);
                pk.y = *reinterpret_cast<unsigned*>(&w1);
                *(uint2*)(msgpk + pid * N + col) = pk;
            } else {
                if (resid) {
                    float2 rv0 = *(const float2*)(resid + r0 * N + col);
                    float2 rv1 = *(const float2*)(resid + r1 * N + col);
                    v0.x += rv0.x; v0.y += rv0.y;
                    v1.x += rv1.x; v1.y += rv1.y;
                }
                *(float2*)(Cout + r0 * N + col) = v0;
                *(float2*)(Cout + r1 * N + col) = v1;
            }
        }
    }
#undef LOADB
}

// ---------------------------------------------------------------------------
// Aggregation v3: 4 pixels x 4 channel-PAIRS (8 channels) per thread.
// msg read as bf16x2 words (one word = 2 channels at one col); unpack is
// exact (bf16 -> f32 = <<16). Accumulate fp32, fused softmax normalization.
// Block (20,8)=160 thr; grid (80, 4).
// ---------------------------------------------------------------------------
__global__ void __launch_bounds__(160) agg_kernel() {
    int h  = blockIdx.x;                       // 0..79
    int tx = threadIdx.x;                      // 0..19 -> pixels 4tx..4tx+3
    int ty = threadIdx.y;                      // 0..7
    int pbase = blockIdx.y * 32 + ty * 4;      // 4 pairs per thread

    __shared__ __align__(16) float saff[K2][W_];
    __shared__ __align__(16) float sinv[W_];
    int tid = ty * 20 + tx;
    const float* affrow = g_aff + h * W_;
    for (int idx = tid; idx < K2 * W_; idx += 160) {
        int k2 = idx / W_;
        int ww = idx - k2 * W_;
        saff[k2][ww] = affrow[k2 * HW + ww];
    }
    __syncthreads();
    if (tid < W_) {
        float s = 0.0f;
#pragma unroll
        for (int k = 0; k < K2; k++) s += saff[k][tid];
        sinv[tid] = 1.0f / s;
    }
    __syncthreads();

    float2 acc[4][4];   // [px][pair]: x = low channel, y = high channel
#pragma unroll
    for (int px = 0; px < 4; px++)
#pragma unroll
        for (int pr = 0; pr < 4; pr++) acc[px][pr] = make_float2(0.f, 0.f);

    const uint4 z4 = make_uint4(0u, 0u, 0u, 0u);
    bool haveA = (tx > 0), haveC = (tx < 19);

    for (int i = 0; i < KS; i++) {
        int hh = h + i - 3;
        if (hh < 0 || hh >= H_) continue;

        float4 s[KS];
#pragma unroll
        for (int j = 0; j < KS; j++)
            s[j] = *(const float4*)&saff[i * KS + j][tx * 4];

#pragma unroll
        for (int pr = 0; pr < 4; pr++) {
            const unsigned* mrow = g_msgpk + (pbase + pr) * HW + hh * W_;
            uint4 va = haveA ? *(const uint4*)(mrow + tx * 4 - 4) : z4;
            uint4 vb = *(const uint4*)(mrow + tx * 4);
            uint4 vc = haveC ? *(const uint4*)(mrow + tx * 4 + 4) : z4;
            unsigned wd[10] = {va.y, va.z, va.w,
                               vb.x, vb.y, vb.z, vb.w,
                               vc.x, vc.y, vc.z};
            float wl[10], wh[10];
#pragma unroll
            for (int q = 0; q < 10; q++) {
                wl[q] = __uint_as_float(wd[q] << 16);
                wh[q] = __uint_as_float(wd[q] & 0xFFFF0000u);
            }
#pragma unroll
            for (int j = 0; j < KS; j++) {
                acc[0][pr].x += wl[j + 0] * s[j].x;
                acc[0][pr].y += wh[j + 0] * s[j].x;
                acc[1][pr].x += wl[j + 1] * s[j].y;
                acc[1][pr].y += wh[j + 1] * s[j].y;
                acc[2][pr].x += wl[j + 2] * s[j].z;
                acc[2][pr].y += wh[j + 2] * s[j].z;
                acc[3][pr].x += wl[j + 3] * s[j].w;
                acc[3][pr].y += wh[j + 3] * s[j].w;
            }
        }
    }

    float4 si = *(const float4*)&sinv[tx * 4];
#pragma unroll
    for (int pr = 0; pr < 4; pr++) {
        int pid = pbase + pr;
        int c0 = (pid >> 3) * 16 + (pid & 7);
        int c1 = c0 + 8;
        float4 lo = make_float4(acc[0][pr].x * si.x, acc[1][pr].x * si.y,
                                acc[2][pr].x * si.z, acc[3][pr].x * si.w);
        float4 hi = make_float4(acc[0][pr].y * si.x, acc[1][pr].y * si.y,
                                acc[2][pr].y * si.z, acc[3][pr].y * si.w);
        *(float4*)(g_agg + c0 * HW + h * W_ + tx * 4) = lo;
        *(float4*)(g_agg + c1 * HW + h * W_ + tx * 4) = hi;
    }
}

// ---------------------------------------------------------------------------
// Launch
// ---------------------------------------------------------------------------
extern "C" void kernel_launch(void* const* d_in, const int* in_sizes, int n_in,
                              void* d_out, int out_size) {
    const float* x      = (const float*)d_in[0];
    const float* coarse = (const float*)d_in[1];
    const float* sigma  = (const float*)d_in[2];
    const float* wfeat  = (const float*)d_in[3];
    const float* wfuse  = (const float*)d_in[4];
    const float* gamma  = (const float*)d_in[5];
    const float* beta   = (const float*)d_in[6];
    const float* mean   = (const float*)d_in[7];
    const float* var    = (const float*)d_in[8];
    float* out = (float*)d_out;

    float *wa1, *wa2, *bias, *agg;
    unsigned* msgpk;
    cudaGetSymbolAddress((void**)&wa1,   g_wa1);
    cudaGetSymbolAddress((void**)&wa2,   g_wa2);
    cudaGetSymbolAddress((void**)&bias,  g_bias);
    cudaGetSymbolAddress((void**)&msgpk, g_msgpk);
    cudaGetSymbolAddress((void**)&agg,   g_agg);

    setup_kernel<<<1280, 128>>>(wfeat, wfuse, gamma, beta, mean, var);
    aff_tap_kernel<<<dim3(H_ / 4, KS), dim3(40, 4)>>>(coarse, sigma);
    // messages = w' @ x + bias  (packed bf16x2 channel-pair output)
    gemm_tc<<<dim3(HW / GBN, C_ / GBM), 256>>>(wa1, x, nullptr, msgpk, bias, nullptr);
    // spatially-varying 7x7 aggregation with fused softmax normalization
    agg_kernel<<<dim3(H_, C_ / 64), dim3(20, 8)>>>();
    // out = x + w_fuse @ agg
    gemm_tc<<<dim3(HW / GBN, C_ / GBM), 256>>>(wa2, agg, out, nullptr, nullptr, x);
}

// round 9
// speedup vs baseline: 3.2390x; 1.0161x over previous
#include <cuda_runtime.h>
#include <cuda_bf16.h>
#include <math.h>

#define H_  80
#define W_  80
#define HW  6400
#define C_  256
#define CP  19
#define KS  7
#define K2  49

// Scratch (allocation-free: __device__ globals)
__device__ float g_bias[C_];           // BN-folded bias for w_feat
__device__ float g_wa1[C_ * C_];       // fragment-ordered BN-folded w_feat
__device__ float g_wa2[C_ * C_];       // fragment-ordered w_fuse
__device__ unsigned g_msgpk[128 * HW]; // messages, bf16x2 channel pairs
__device__ float g_agg[C_ * HW];       // aggregated (fp32)
__device__ float g_aff[K2 * HW];       // unnormalized affinity exp(exp(-d/denom))

// ---------------------------------------------------------------------------
// Front kernel: blockIdx-partitioned union of
//   [0,140)      affinity taps (20 x 7 layout, 160 thr = 40 px * 4 rows)
//   [140,1164)   weight rearrange (BN scale folded into w_feat)
//   [1164,1420)  BN-folded bias reduction
// Fragment order: [kb 0..31][mb 0..15][lane][a0..a3].
// ---------------------------------------------------------------------------
__global__ void __launch_bounds__(160) front_kernel(
        const float* __restrict__ coarse, const float* __restrict__ sigma,
        const float* __restrict__ wfeat,  const float* __restrict__ wfuse,
        const float* __restrict__ gamma,  const float* __restrict__ beta,
        const float* __restrict__ mean,   const float* __restrict__ var) {
    int b = blockIdx.x;
    int t = threadIdx.x;

    if (b < 140) {
        // ---- affinity: 2 pixels per thread, sliding window ----
        int tx = t % 40;                  // 0..39 -> pixels 2tx, 2tx+1
        int h  = (b % 20) * 4 + t / 40;
        int i  = b / 20;                  // tap row 0..6
        int b0 = tx * 2;

        float sr = fmaxf(sigma[0], 0.0f);
        float invd = 1.0f / (2.0f * sr * sr + 1e-8f);

        int hh = h + i - 3;
        bool rowok = (hh >= 0) && (hh < H_);
        const float* crow = coarse + h * W_;
        const float* nrow = coarse + (rowok ? hh : 0) * W_;

        bool v[5];
#pragma unroll
        for (int l = 0; l < 5; l++) {
            int col = b0 - 4 + 2 * l;
            v[l] = rowok && (col >= 0) && (col <= W_ - 2);
        }

        float d[KS][2];
#pragma unroll
        for (int j = 0; j < KS; j++) { d[j][0] = 0.0f; d[j][1] = 0.0f; }

        const float2 z2 = make_float2(0.0f, 0.0f);
#pragma unroll
        for (int cp = 0; cp < CP; cp++) {
            float2 cen = *(const float2*)(crow + cp * HW + b0);
            const float* nb = nrow + cp * HW;
            float win[8];
            float2 L;
            L = v[0] ? *(const float2*)(nb + b0 - 4) : z2; win[0] = L.y;
            L = v[1] ? *(const float2*)(nb + b0 - 2) : z2; win[1] = L.x; win[2] = L.y;
            L = v[2] ? *(const float2*)(nb + b0)     : z2; win[3] = L.x; win[4] = L.y;
            L = v[3] ? *(const float2*)(nb + b0 + 2) : z2; win[5] = L.x; win[6] = L.y;
            L = v[4] ? *(const float2*)(nb + b0 + 4) : z2; win[7] = L.x;
#pragma unroll
            for (int j = 0; j < KS; j++) {
                float t0 = win[j]     - cen.x; d[j][0] += t0 * t0;
                float t1 = win[j + 1] - cen.y; d[j][1] += t1 * t1;
            }
        }

        int p = h * W_ + b0;
#pragma unroll
        for (int j = 0; j < KS; j++) {
            g_aff[(i * KS + j) * HW + p]     = __expf(__expf(-d[j][0] * invd));
            g_aff[(i * KS + j) * HW + p + 1] = __expf(__expf(-d[j][1] * invd));
        }
    } else if (b < 1164) {
        // ---- weight rearrange ----
        if (t < 128) {
            int bb = b - 140;
            int w2 = bb >> 9;             // 0: wfeat (scaled), 1: wfuse
            bb &= 511;
            int kb = bb & 31, mb = bb >> 5;
            int lane = t & 31, q = t >> 5;
            int gid = lane >> 2, tig = lane & 3;
            int row = mb * 16 + gid + (q & 1) * 8;
            int col = kb * 8 + tig + (q >> 1) * 4;
            const float* src = w2 ? wfuse : wfeat;
            float v = src[row * C_ + col];
            if (!w2) v *= gamma[col] * rsqrtf(var[col] + 1e-5f);
            float* dst = w2 ? g_wa2 : g_wa1;
            dst[((kb * 16 + mb) * 32 + lane) * 4 + q] = v;
        }
    } else {
        // ---- bias reduction ----
        int o = b - 1164;                 // 0..255
        float s = 0.0f;
        for (int c = t; c < C_; c += 160) {
            float a = gamma[c] * rsqrtf(var[c] + 1e-5f);
            s += wfeat[o * C_ + c] * (beta[c] - mean[c] * a);
        }
#pragma unroll
        for (int off = 16; off; off >>= 1) s += __shfl_xor_sync(~0u, s, off);
        __shared__ float red[5];
        if ((t & 31) == 0) red[t >> 5] = s;
        __syncthreads();
        if (t == 0) g_bias[o] = red[0] + red[1] + red[2] + red[3] + red[4];
    }
}

// ---------------------------------------------------------------------------
// Tensor-core GEMM (tf32 mma.sync), A-frags via LDG from arranged buffer,
// B via 3-stage cp.async. Tile 64x64, BK=32, 8 warps (2x4), warp 32x16.
// Epilogue: if msgpk != null, emit bf16x2 channel-pairs (rows r, r+8);
// else fp32 (+resid).
// ---------------------------------------------------------------------------
#define GBM 64
#define GBN 64
#define GBK 32
#define BSTR (GBN + 8)
#define NSTG 3

__device__ __forceinline__ void cp16(void* smem, const void* gmem) {
    unsigned s = (unsigned)__cvta_generic_to_shared(smem);
    asm volatile("cp.async.ca.shared.global [%0], [%1], 16;\n" :: "r"(s), "l"(gmem));
}

__device__ __forceinline__ void mma_tf32(float* c, const unsigned* a, const unsigned* b) {
    asm volatile(
        "mma.sync.aligned.m16n8k8.row.col.f32.tf32.tf32.f32 "
        "{%0,%1,%2,%3}, {%4,%5,%6,%7}, {%8,%9}, {%0,%1,%2,%3};\n"
        : "+f"(c[0]), "+f"(c[1]), "+f"(c[2]), "+f"(c[3])
        : "r"(a[0]), "r"(a[1]), "r"(a[2]), "r"(a[3]), "r"(b[0]), "r"(b[1]));
}

__global__ void __launch_bounds__(256) gemm_tc(
        const float* __restrict__ Afrag,
        const float* __restrict__ B,
        float* __restrict__ Cout,          // used when msgpk == null
        unsigned* __restrict__ msgpk,      // packed output (or null)
        const float* __restrict__ bias,
        const float* __restrict__ resid) {
    const int N = HW;
    __shared__ __align__(16) float Bs[NSTG][GBK][BSTR];

    int t    = threadIdx.x;
    int warp = t >> 5, lane = t & 31;
    int gid  = lane >> 2, tig = lane & 3;
    int wm   = warp >> 2, wn = warp & 3;
    int m0   = blockIdx.y * GBM, n0 = blockIdx.x * GBN;
    int mb0  = blockIdx.y * 4 + wm * 2;

    int kr0 = t >> 4;
    int co  = (t & 15) * 4;

    float acc[2][2][4];
#pragma unroll
    for (int mi = 0; mi < 2; mi++)
#pragma unroll
        for (int ni = 0; ni < 2; ni++)
#pragma unroll
            for (int q = 0; q < 4; q++) acc[mi][ni][q] = 0.0f;

#define LOADB(s, k0)                                                          \
    {                                                                          \
        cp16(&Bs[s][kr0][co],      B + ((k0) + kr0) * N + n0 + co);            \
        cp16(&Bs[s][kr0 + 16][co], B + ((k0) + kr0 + 16) * N + n0 + co);       \
        asm volatile("cp.async.commit_group;\n");                              \
    }

    LOADB(0, 0);
    LOADB(1, GBK);

    const int NIT = C_ / GBK;   // 8
    for (int it = 0; it < NIT; it++) {
        if (it + 1 < NIT) asm volatile("cp.async.wait_group 1;\n");
        else              asm volatile("cp.async.wait_group 0;\n");
        __syncthreads();
        if (it + 2 < NIT) LOADB((it + 2) % NSTG, (it + 2) * GBK);

        int s = it % NSTG;
#pragma unroll
        for (int kk = 0; kk < GBK / 8; kk++) {
            int kbg = it * 4 + kk;
            float4 a0 = *(const float4*)(Afrag + ((kbg * 16 + mb0) * 32 + lane) * 4);
            float4 a1 = *(const float4*)(Afrag + ((kbg * 16 + mb0 + 1) * 32 + lane) * 4);
            unsigned aR[2][4];
            aR[0][0] = __float_as_uint(a0.x); aR[0][1] = __float_as_uint(a0.y);
            aR[0][2] = __float_as_uint(a0.z); aR[0][3] = __float_as_uint(a0.w);
            aR[1][0] = __float_as_uint(a1.x); aR[1][1] = __float_as_uint(a1.y);
            aR[1][2] = __float_as_uint(a1.z); aR[1][3] = __float_as_uint(a1.w);

            unsigned bR[2][2];
#pragma unroll
            for (int ni = 0; ni < 2; ni++) {
                int cN = wn * 16 + ni * 8 + gid;
                bR[ni][0] = __float_as_uint(Bs[s][kk * 8 + tig][cN]);
                bR[ni][1] = __float_as_uint(Bs[s][kk * 8 + tig + 4][cN]);
            }
#pragma unroll
            for (int mi = 0; mi < 2; mi++)
#pragma unroll
                for (int ni = 0; ni < 2; ni++)
                    mma_tf32(acc[mi][ni], aR[mi], bR[ni]);
        }
        __syncthreads();
    }

#pragma unroll
    for (int mi = 0; mi < 2; mi++) {
        int r0 = m0 + wm * 32 + mi * 16 + gid;
        int r1 = r0 + 8;
        float b0v = bias ? bias[r0] : 0.0f;
        float b1v = bias ? bias[r1] : 0.0f;
#pragma unroll
        for (int ni = 0; ni < 2; ni++) {
            int col = n0 + wn * 16 + ni * 8 + tig * 2;
            float2 v0, v1;
            v0.x = acc[mi][ni][0] + b0v;
            v0.y = acc[mi][ni][1] + b0v;
            v1.x = acc[mi][ni][2] + b1v;
            v1.y = acc[mi][ni][3] + b1v;
            if (msgpk) {
                int pid = ((m0 >> 4) + wm * 2 + mi) * 8 + gid;
                __nv_bfloat162 w0 = __floats2bfloat162_rn(v0.x, v1.x);
                __nv_bfloat162 w1 = __floats2bfloat162_rn(v0.y, v1.y);
                uint2 pk;
                pk.x = *reinterpret_cast<unsigned*>(&w0);
                pk.y = *reinterpret_cast<unsigned*>(&w1);
                *(uint2*)(msgpk + pid * N + col) = pk;
            } else {
                if (resid) {
                    float2 rv0 = *(const float2*)(resid + r0 * N + col);
                    float2 rv1 = *(const float2*)(resid + r1 * N + col);
                    v0.x += rv0.x; v0.y += rv0.y;
                    v1.x += rv1.x; v1.y += rv1.y;
                }
                *(float2*)(Cout + r0 * N + col) = v0;
                *(float2*)(Cout + r1 * N + col) = v1;
            }
        }
    }
#undef LOADB
}

// ---------------------------------------------------------------------------
// Aggregation v4: 4 pixels x 2 channel-pairs per thread (occupancy 2x R7).
// Block (20,16)=320 thr, grid (80,4). bf16x2 unpack is exact (<<16).
// ---------------------------------------------------------------------------
__global__ void __launch_bounds__(320) agg_kernel() {
    int h  = blockIdx.x;                       // 0..79
    int tx = threadIdx.x;                      // 0..19 -> pixels 4tx..4tx+3
    int ty = threadIdx.y;                      // 0..15
    int pbase = blockIdx.y * 32 + ty * 2;      // 2 pairs per thread

    __shared__ __align__(16) float saff[K2][W_];
    __shared__ __align__(16) float sinv[W_];
    int tid = ty * 20 + tx;
    const float* affrow = g_aff + h * W_;
    for (int idx = tid; idx < K2 * W_; idx += 320) {
        int k2 = idx / W_;
        int ww = idx - k2 * W_;
        saff[k2][ww] = affrow[k2 * HW + ww];
    }
    __syncthreads();
    if (tid < W_) {
        float s = 0.0f;
#pragma unroll
        for (int k = 0; k < K2; k++) s += saff[k][tid];
        sinv[tid] = 1.0f / s;
    }
    __syncthreads();

    float2 acc[4][2];   // [px][pair]: x = low channel, y = high channel
#pragma unroll
    for (int px = 0; px < 4; px++)
#pragma unroll
        for (int pr = 0; pr < 2; pr++) acc[px][pr] = make_float2(0.f, 0.f);

    const uint4 z4 = make_uint4(0u, 0u, 0u, 0u);
    bool haveA = (tx > 0), haveC = (tx < 19);

    for (int i = 0; i < KS; i++) {
        int hh = h + i - 3;
        if (hh < 0 || hh >= H_) continue;

        float4 s[KS];
#pragma unroll
        for (int j = 0; j < KS; j++)
            s[j] = *(const float4*)&saff[i * KS + j][tx * 4];

#pragma unroll
        for (int pr = 0; pr < 2; pr++) {
            const unsigned* mrow = g_msgpk + (pbase + pr) * HW + hh * W_;
            uint4 va = haveA ? *(const uint4*)(mrow + tx * 4 - 4) : z4;
            uint4 vb = *(const uint4*)(mrow + tx * 4);
            uint4 vc = haveC ? *(const uint4*)(mrow + tx * 4 + 4) : z4;
            unsigned wd[10] = {va.y, va.z, va.w,
                               vb.x, vb.y, vb.z, vb.w,
                               vc.x, vc.y, vc.z};
            float wl[10], wh[10];
#pragma unroll
            for (int q = 0; q < 10; q++) {
                wl[q] = __uint_as_float(wd[q] << 16);
                wh[q] = __uint_as_float(wd[q] & 0xFFFF0000u);
            }
#pragma unroll
            for (int j = 0; j < KS; j++) {
                acc[0][pr].x += wl[j + 0] * s[j].x;
                acc[0][pr].y += wh[j + 0] * s[j].x;
                acc[1][pr].x += wl[j + 1] * s[j].y;
                acc[1][pr].y += wh[j + 1] * s[j].y;
                acc[2][pr].x += wl[j + 2] * s[j].z;
                acc[2][pr].y += wh[j + 2] * s[j].z;
                acc[3][pr].x += wl[j + 3] * s[j].w;
                acc[3][pr].y += wh[j + 3] * s[j].w;
            }
        }
    }

    float4 si = *(const float4*)&sinv[tx * 4];
#pragma unroll
    for (int pr = 0; pr < 2; pr++) {
        int pid = pbase + pr;
        int c0 = (pid >> 3) * 16 + (pid & 7);
        int c1 = c0 + 8;
        float4 lo = make_float4(acc[0][pr].x * si.x, acc[1][pr].x * si.y,
                                acc[2][pr].x * si.z, acc[3][pr].x * si.w);
        float4 hi = make_float4(acc[0][pr].y * si.x, acc[1][pr].y * si.y,
                                acc[2][pr].y * si.z, acc[3][pr].y * si.w);
        *(float4*)(g_agg + c0 * HW + h * W_ + tx * 4) = lo;
        *(float4*)(g_agg + c1 * HW + h * W_ + tx * 4) = hi;
    }
}

// ---------------------------------------------------------------------------
// Launch
// ---------------------------------------------------------------------------
extern "C" void kernel_launch(void* const* d_in, const int* in_sizes, int n_in,
                              void* d_out, int out_size) {
    const float* x      = (const float*)d_in[0];
    const float* coarse = (const float*)d_in[1];
    const float* sigma  = (const float*)d_in[2];
    const float* wfeat  = (const float*)d_in[3];
    const float* wfuse  = (const float*)d_in[4];
    const float* gamma  = (const float*)d_in[5];
    const float* beta   = (const float*)d_in[6];
    const float* mean   = (const float*)d_in[7];
    const float* var    = (const float*)d_in[8];
    float* out = (float*)d_out;

    float *wa1, *wa2, *bias, *agg;
    unsigned* msgpk;
    cudaGetSymbolAddress((void**)&wa1,   g_wa1);
    cudaGetSymbolAddress((void**)&wa2,   g_wa2);
    cudaGetSymbolAddress((void**)&bias,  g_bias);
    cudaGetSymbolAddress((void**)&msgpk, g_msgpk);
    cudaGetSymbolAddress((void**)&agg,   g_agg);

    // affinity taps + weight rearrange + bias, one launch
    front_kernel<<<1420, 160>>>(coarse, sigma, wfeat, wfuse,
                                gamma, beta, mean, var);
    // messages = w' @ x + bias  (packed bf16x2 channel-pair output)
    gemm_tc<<<dim3(HW / GBN, C_ / GBM), 256>>>(wa1, x, nullptr, msgpk, bias, nullptr);
    // spatially-varying 7x7 aggregation with fused softmax normalization
    agg_kernel<<<dim3(H_, C_ / 64), dim3(20, 16)>>>();
    // out = x + w_fuse @ agg
    gemm_tc<<<dim3(HW / GBN, C_ / GBM), 256>>>(wa2, agg, out, nullptr, nullptr, x);
}

// round 10
// speedup vs baseline: 3.2605x; 1.0066x over previous
#include <cuda_runtime.h>
#include <cuda_bf16.h>
#include <math.h>

#define H_  80
#define W_  80
#define HW  6400
#define C_  256
#define CP  19
#define KS  7
#define K2  49

// Scratch (allocation-free: __device__ globals)
__device__ float g_bias[C_];           // BN-folded bias for w_feat
__device__ float g_wa1[C_ * C_];       // fragment-ordered BN-folded w_feat
__device__ float g_wa2[C_ * C_];       // fragment-ordered w_fuse
__device__ unsigned g_msgpk[128 * HW]; // messages, bf16x2 channel pairs
__device__ float g_agg[C_ * HW];       // aggregated (fp32)
__device__ float g_aff[K2 * HW];       // unnormalized affinity exp(exp(-d/denom))

// ---------------------------------------------------------------------------
// Front kernel: blockIdx-partitioned union of
//   [0,140)      affinity taps (20 x 7 layout, 160 thr = 40 px * 4 rows)
//   [140,1164)   weight rearrange (BN scale folded into w_feat)
//   [1164,1420)  BN-folded bias reduction
// Fragment order: [kb 0..31][mb 0..15][lane][a0..a3].
// ---------------------------------------------------------------------------
__global__ void __launch_bounds__(160) front_kernel(
        const float* __restrict__ coarse, const float* __restrict__ sigma,
        const float* __restrict__ wfeat,  const float* __restrict__ wfuse,
        const float* __restrict__ gamma,  const float* __restrict__ beta,
        const float* __restrict__ mean,   const float* __restrict__ var) {
    int b = blockIdx.x;
    int t = threadIdx.x;

    if (b < 140) {
        // ---- affinity: 2 pixels per thread, sliding window ----
        int tx = t % 40;                  // 0..39 -> pixels 2tx, 2tx+1
        int h  = (b % 20) * 4 + t / 40;
        int i  = b / 20;                  // tap row 0..6
        int b0 = tx * 2;

        float sr = fmaxf(sigma[0], 0.0f);
        float invd = 1.0f / (2.0f * sr * sr + 1e-8f);

        int hh = h + i - 3;
        bool rowok = (hh >= 0) && (hh < H_);
        const float* crow = coarse + h * W_;
        const float* nrow = coarse + (rowok ? hh : 0) * W_;

        bool v[5];
#pragma unroll
        for (int l = 0; l < 5; l++) {
            int col = b0 - 4 + 2 * l;
            v[l] = rowok && (col >= 0) && (col <= W_ - 2);
        }

        float d[KS][2];
#pragma unroll
        for (int j = 0; j < KS; j++) { d[j][0] = 0.0f; d[j][1] = 0.0f; }

        const float2 z2 = make_float2(0.0f, 0.0f);
#pragma unroll
        for (int cp = 0; cp < CP; cp++) {
            float2 cen = *(const float2*)(crow + cp * HW + b0);
            const float* nb = nrow + cp * HW;
            float win[8];
            float2 L;
            L = v[0] ? *(const float2*)(nb + b0 - 4) : z2; win[0] = L.y;
            L = v[1] ? *(const float2*)(nb + b0 - 2) : z2; win[1] = L.x; win[2] = L.y;
            L = v[2] ? *(const float2*)(nb + b0)     : z2; win[3] = L.x; win[4] = L.y;
            L = v[3] ? *(const float2*)(nb + b0 + 2) : z2; win[5] = L.x; win[6] = L.y;
            L = v[4] ? *(const float2*)(nb + b0 + 4) : z2; win[7] = L.x;
#pragma unroll
            for (int j = 0; j < KS; j++) {
                float t0 = win[j]     - cen.x; d[j][0] += t0 * t0;
                float t1 = win[j + 1] - cen.y; d[j][1] += t1 * t1;
            }
        }

        int p = h * W_ + b0;
#pragma unroll
        for (int j = 0; j < KS; j++) {
            g_aff[(i * KS + j) * HW + p]     = __expf(__expf(-d[j][0] * invd));
            g_aff[(i * KS + j) * HW + p + 1] = __expf(__expf(-d[j][1] * invd));
        }
    } else if (b < 1164) {
        // ---- weight rearrange ----
        if (t < 128) {
            int bb = b - 140;
            int w2 = bb >> 9;             // 0: wfeat (scaled), 1: wfuse
            bb &= 511;
            int kb = bb & 31, mb = bb >> 5;
            int lane = t & 31, q = t >> 5;
            int gid = lane >> 2, tig = lane & 3;
            int row = mb * 16 + gid + (q & 1) * 8;
            int col = kb * 8 + tig + (q >> 1) * 4;
            const float* src = w2 ? wfuse : wfeat;
            float v = src[row * C_ + col];
            if (!w2) v *= gamma[col] * rsqrtf(var[col] + 1e-5f);
            float* dst = w2 ? g_wa2 : g_wa1;
            dst[((kb * 16 + mb) * 32 + lane) * 4 + q] = v;
        }
    } else {
        // ---- bias reduction ----
        int o = b - 1164;                 // 0..255
        float s = 0.0f;
        for (int c = t; c < C_; c += 160) {
            float a = gamma[c] * rsqrtf(var[c] + 1e-5f);
            s += wfeat[o * C_ + c] * (beta[c] - mean[c] * a);
        }
#pragma unroll
        for (int off = 16; off; off >>= 1) s += __shfl_xor_sync(~0u, s, off);
        __shared__ float red[5];
        if ((t & 31) == 0) red[t >> 5] = s;
        __syncthreads();
        if (t == 0) g_bias[o] = red[0] + red[1] + red[2] + red[3] + red[4];
    }
}

// ---------------------------------------------------------------------------
// Tensor-core GEMM (tf32 mma.sync). A-frags via LDG with ITERATION-LEVEL
// REGISTER DOUBLE BUFFERING (prefetch it+1's 8 LDG.128 before computing it).
// B via 3-stage cp.async. Tile 64x64, BK=32, 8 warps (2x4), warp 32x16.
// ---------------------------------------------------------------------------
#define GBM 64
#define GBN 64
#define GBK 32
#define BSTR (GBN + 8)
#define NSTG 3

__device__ __forceinline__ void cp16(void* smem, const void* gmem) {
    unsigned s = (unsigned)__cvta_generic_to_shared(smem);
    asm volatile("cp.async.ca.shared.global [%0], [%1], 16;\n" :: "r"(s), "l"(gmem));
}

__device__ __forceinline__ void mma_tf32(float* c, const unsigned* a, const unsigned* b) {
    asm volatile(
        "mma.sync.aligned.m16n8k8.row.col.f32.tf32.tf32.f32 "
        "{%0,%1,%2,%3}, {%4,%5,%6,%7}, {%8,%9}, {%0,%1,%2,%3};\n"
        : "+f"(c[0]), "+f"(c[1]), "+f"(c[2]), "+f"(c[3])
        : "r"(a[0]), "r"(a[1]), "r"(a[2]), "r"(a[3]), "r"(b[0]), "r"(b[1]));
}

__global__ void __launch_bounds__(256, 2) gemm_tc(
        const float* __restrict__ Afrag,
        const float* __restrict__ B,
        float* __restrict__ Cout,          // used when msgpk == null
        unsigned* __restrict__ msgpk,      // packed output (or null)
        const float* __restrict__ bias,
        const float* __restrict__ resid) {
    const int N = HW;
    __shared__ __align__(16) float Bs[NSTG][GBK][BSTR];

    int t    = threadIdx.x;
    int warp = t >> 5, lane = t & 31;
    int gid  = lane >> 2, tig = lane & 3;
    int wm   = warp >> 2, wn = warp & 3;
    int m0   = blockIdx.y * GBM, n0 = blockIdx.x * GBN;
    int mb0  = blockIdx.y * 4 + wm * 2;

    int kr0 = t >> 4;
    int co  = (t & 15) * 4;

    float acc[2][2][4];
#pragma unroll
    for (int mi = 0; mi < 2; mi++)
#pragma unroll
        for (int ni = 0; ni < 2; ni++)
#pragma unroll
            for (int q = 0; q < 4; q++) acc[mi][ni][q] = 0.0f;

    // A-frag double buffer: [buf][kk][mi][4]
    float4 areg[2][4][2];
    const float* abase = Afrag + (mb0 * 32 + lane) * 4;  // + kbg*16*32*4

#define LOADA(buf, it)                                                        \
    {                                                                          \
        _Pragma("unroll")                                                      \
        for (int kk = 0; kk < 4; kk++) {                                       \
            int kbg = (it) * 4 + kk;                                           \
            areg[buf][kk][0] = *(const float4*)(abase + kbg * 2048);           \
            areg[buf][kk][1] = *(const float4*)(abase + kbg * 2048 + 128);     \
        }                                                                      \
    }

#define LOADB(s, k0)                                                          \
    {                                                                          \
        cp16(&Bs[s][kr0][co],      B + ((k0) + kr0) * N + n0 + co);            \
        cp16(&Bs[s][kr0 + 16][co], B + ((k0) + kr0 + 16) * N + n0 + co);       \
        asm volatile("cp.async.commit_group;\n");                              \
    }

    LOADB(0, 0);
    LOADB(1, GBK);
    LOADA(0, 0);

    const int NIT = C_ / GBK;   // 8
    for (int it = 0; it < NIT; it++) {
        if (it + 1 < NIT) asm volatile("cp.async.wait_group 1;\n");
        else              asm volatile("cp.async.wait_group 0;\n");
        __syncthreads();
        if (it + 2 < NIT) LOADB((it + 2) % NSTG, (it + 2) * GBK);
        if (it + 1 < NIT) LOADA((it + 1) & 1, it + 1);   // prefetch next A

        int s  = it % NSTG;
        int ab = it & 1;
#pragma unroll
        for (int kk = 0; kk < GBK / 8; kk++) {
            unsigned aR[2][4];
#pragma unroll
            for (int mi = 0; mi < 2; mi++) {
                aR[mi][0] = __float_as_uint(areg[ab][kk][mi].x);
                aR[mi][1] = __float_as_uint(areg[ab][kk][mi].y);
                aR[mi][2] = __float_as_uint(areg[ab][kk][mi].z);
                aR[mi][3] = __float_as_uint(areg[ab][kk][mi].w);
            }
            unsigned bR[2][2];
#pragma unroll
            for (int ni = 0; ni < 2; ni++) {
                int cN = wn * 16 + ni * 8 + gid;
                bR[ni][0] = __float_as_uint(Bs[s][kk * 8 + tig][cN]);
                bR[ni][1] = __float_as_uint(Bs[s][kk * 8 + tig + 4][cN]);
            }
#pragma unroll
            for (int mi = 0; mi < 2; mi++)
#pragma unroll
                for (int ni = 0; ni < 2; ni++)
                    mma_tf32(acc[mi][ni], aR[mi], bR[ni]);
        }
        __syncthreads();
    }

#pragma unroll
    for (int mi = 0; mi < 2; mi++) {
        int r0 = m0 + wm * 32 + mi * 16 + gid;
        int r1 = r0 + 8;
        float b0v = bias ? bias[r0] : 0.0f;
        float b1v = bias ? bias[r1] : 0.0f;
#pragma unroll
        for (int ni = 0; ni < 2; ni++) {
            int col = n0 + wn * 16 + ni * 8 + tig * 2;
            float2 v0, v1;
            v0.x = acc[mi][ni][0] + b0v;
            v0.y = acc[mi][ni][1] + b0v;
            v1.x = acc[mi][ni][2] + b1v;
            v1.y = acc[mi][ni][3] + b1v;
            if (msgpk) {
                int pid = ((m0 >> 4) + wm * 2 + mi) * 8 + gid;
                __nv_bfloat162 w0 = __floats2bfloat162_rn(v0.x, v1.x);
                __nv_bfloat162 w1 = __floats2bfloat162_rn(v0.y, v1.y);
                uint2 pk;
                pk.x = *reinterpret_cast<unsigned*>(&w0);
                pk.y = *reinterpret_cast<unsigned*>(&w1);
                *(uint2*)(msgpk + pid * N + col) = pk;
            } else {
                if (resid) {
                    float2 rv0 = *(const float2*)(resid + r0 * N + col);
                    float2 rv1 = *(const float2*)(resid + r1 * N + col);
                    v0.x += rv0.x; v0.y += rv0.y;
                    v1.x += rv1.x; v1.y += rv1.y;
                }
                *(float2*)(Cout + r0 * N + col) = v0;
                *(float2*)(Cout + r1 * N + col) = v1;
            }
        }
    }
#undef LOADB
#undef LOADA
}

// ---------------------------------------------------------------------------
// Aggregation: 4 pixels x 2 channel-pairs per thread.
// Block (20,16)=320 thr, grid (80,4). bf16x2 unpack is exact (<<16).
// ---------------------------------------------------------------------------
__global__ void __launch_bounds__(320) agg_kernel() {
    int h  = blockIdx.x;                       // 0..79
    int tx = threadIdx.x;                      // 0..19 -> pixels 4tx..4tx+3
    int ty = threadIdx.y;                      // 0..15
    int pbase = blockIdx.y * 32 + ty * 2;      // 2 pairs per thread

    __shared__ __align__(16) float saff[K2][W_];
    __shared__ __align__(16) float sinv[W_];
    int tid = ty * 20 + tx;
    const float* affrow = g_aff + h * W_;
    for (int idx = tid; idx < K2 * W_; idx += 320) {
        int k2 = idx / W_;
        int ww = idx - k2 * W_;
        saff[k2][ww] = affrow[k2 * HW + ww];
    }
    __syncthreads();
    if (tid < W_) {
        float s = 0.0f;
#pragma unroll
        for (int k = 0; k < K2; k++) s += saff[k][tid];
        sinv[tid] = 1.0f / s;
    }
    __syncthreads();

    float2 acc[4][2];   // [px][pair]: x = low channel, y = high channel
#pragma unroll
    for (int px = 0; px < 4; px++)
#pragma unroll
        for (int pr = 0; pr < 2; pr++) acc[px][pr] = make_float2(0.f, 0.f);

    const uint4 z4 = make_uint4(0u, 0u, 0u, 0u);
    bool haveA = (tx > 0), haveC = (tx < 19);

    for (int i = 0; i < KS; i++) {
        int hh = h + i - 3;
        if (hh < 0 || hh >= H_) continue;

        float4 s[KS];
#pragma unroll
        for (int j = 0; j < KS; j++)
            s[j] = *(const float4*)&saff[i * KS + j][tx * 4];

#pragma unroll
        for (int pr = 0; pr < 2; pr++) {
            const unsigned* mrow = g_msgpk + (pbase + pr) * HW + hh * W_;
            uint4 va = haveA ? *(const uint4*)(mrow + tx * 4 - 4) : z4;
            uint4 vb = *(const uint4*)(mrow + tx * 4);
            uint4 vc = haveC ? *(const uint4*)(mrow + tx * 4 + 4) : z4;
            unsigned wd[10] = {va.y, va.z, va.w,
                               vb.x, vb.y, vb.z, vb.w,
                               vc.x, vc.y, vc.z};
            float wl[10], wh[10];
#pragma unroll
            for (int q = 0; q < 10; q++) {
                wl[q] = __uint_as_float(wd[q] << 16);
                wh[q] = __uint_as_float(wd[q] & 0xFFFF0000u);
            }
#pragma unroll
            for (int j = 0; j < KS; j++) {
                acc[0][pr].x += wl[j + 0] * s[j].x;
                acc[0][pr].y += wh[j + 0] * s[j].x;
                acc[1][pr].x += wl[j + 1] * s[j].y;
                acc[1][pr].y += wh[j + 1] * s[j].y;
                acc[2][pr].x += wl[j + 2] * s[j].z;
                acc[2][pr].y += wh[j + 2] * s[j].z;
                acc[3][pr].x += wl[j + 3] * s[j].w;
                acc[3][pr].y += wh[j + 3] * s[j].w;
            }
        }
    }

    float4 si = *(const float4*)&sinv[tx * 4];
#pragma unroll
    for (int pr = 0; pr < 2; pr++) {
        int pid = pbase + pr;
        int c0 = (pid >> 3) * 16 + (pid & 7);
        int c1 = c0 + 8;
        float4 lo = make_float4(acc[0][pr].x * si.x, acc[1][pr].x * si.y,
                                acc[2][pr].x * si.z, acc[3][pr].x * si.w);
        float4 hi = make_float4(acc[0][pr].y * si.x, acc[1][pr].y * si.y,
                                acc[2][pr].y * si.z, acc[3][pr].y * si.w);
        *(float4*)(g_agg + c0 * HW + h * W_ + tx * 4) = lo;
        *(float4*)(g_agg + c1 * HW + h * W_ + tx * 4) = hi;
    }
}

// ---------------------------------------------------------------------------
// Launch
// ---------------------------------------------------------------------------
extern "C" void kernel_launch(void* const* d_in, const int* in_sizes, int n_in,
                              void* d_out, int out_size) {
    const float* x      = (const float*)d_in[0];
    const float* coarse = (const float*)d_in[1];
    const float* sigma  = (const float*)d_in[2];
    const float* wfeat  = (const float*)d_in[3];
    const float* wfuse  = (const float*)d_in[4];
    const float* gamma  = (const float*)d_in[5];
    const float* beta   = (const float*)d_in[6];
    const float* mean   = (const float*)d_in[7];
    const float* var    = (const float*)d_in[8];
    float* out = (float*)d_out;

    float *wa1, *wa2, *bias, *agg;
    unsigned* msgpk;
    cudaGetSymbolAddress((void**)&wa1,   g_wa1);
    cudaGetSymbolAddress((void**)&wa2,   g_wa2);
    cudaGetSymbolAddress((void**)&bias,  g_bias);
    cudaGetSymbolAddress((void**)&msgpk, g_msgpk);
    cudaGetSymbolAddress((void**)&agg,   g_agg);

    // affinity taps + weight rearrange + bias, one launch
    front_kernel<<<1420, 160>>>(coarse, sigma, wfeat, wfuse,
                                gamma, beta, mean, var);
    // messages = w' @ x + bias  (packed bf16x2 channel-pair output)
    gemm_tc<<<dim3(HW / GBN, C_ / GBM), 256>>>(wa1, x, nullptr, msgpk, bias, nullptr);
    // spatially-varying 7x7 aggregation with fused softmax normalization
    agg_kernel<<<dim3(H_, C_ / 64), dim3(20, 16)>>>();
    // out = x + w_fuse @ agg
    gemm_tc<<<dim3(HW / GBN, C_ / GBM), 256>>>(wa2, agg, out, nullptr, nullptr, x);
}